// round 14
// baseline (speedup 1.0000x reference)
#include <cuda_runtime.h>
#include <math.h>

typedef unsigned long long ull;

#define BATCH 512
#define TFEAT 204
#define NFEAT 20
#define CDIM  256
#define SUBD  40
#define NSLICE 32
#define NGRP   4
#define GROWS  128
#define NCTA   128
#define NTHR   256
#define KCH    32
#define XSTR   36

// ---------------- device globals ----------------
__device__ float g_bufA[BATCH * TFEAT * CDIM];   // fd1 out
__device__ float g_cp[BATCH * 200 * CDIM];       // CP = cond @ d1_w[:, :256]^T + d1_b

__device__ float g_fd1t[NFEAT * CDIM];
__device__ float g_c1t[768 * CDIM];
__device__ float g_c2t[768 * CDIM];
__device__ float g_fd2t[CDIM * CDIM];
__device__ float g_d1t[CDIM * CDIM];             // transposed first-256-k of d1_w

__device__ float g_t1[BATCH * CDIM];
__device__ float g_t2[BATCH * CDIM];

// zeroed state: h ping-pong(6 planes) + prev + padded barrier counters (one memset)
#define STATE_H     0
#define STATE_PREV  (6 * BATCH * CDIM)
#define STATE_BAR   (STATE_PREV + BATCH * SUBD)
#define STATE_TOT   (STATE_BAR + NGRP * 32)
__device__ float g_state[STATE_TOT];
#define G_H(p, l)   (g_state + ((p) * 3 + (l)) * (BATCH * CDIM))
#define G_PREV      (g_state + STATE_PREV)
#define G_BAR(grp)  ((int*)(g_state + STATE_BAR) + (grp) * 32)   // 128B apart

// ---------------- smem layout for AR (floats) ----------------
#define PDK 260
#define O_WD2  0
#define O_GRU0 2080
#define GRU_STRIDE 12480
#define O_WOW  (O_GRU0 + 3 * GRU_STRIDE)  // 39520
#define O_D1P  (O_WOW + 520)              // [8][44]
#define O_BD2  (O_D1P + 352)
#define O_BI0  (O_BD2 + 8)
#define O_OB   (O_BI0 + 144)
#define O_XS   40548
#define O_HS   (O_XS + 4608)
#define SM_FLOATS (O_HS + 4608)
#define SM_BYTES  (SM_FLOATS * 4)

// ---------------- f32x2 helpers ----------------
__device__ __forceinline__ void fma2(ull& d, ull a, ull b) {
    asm("fma.rn.f32x2 %0, %1, %2, %0;" : "+l"(d) : "l"(a), "l"(b));
}
__device__ __forceinline__ float red2(ull v) {
    union { ull u; float2 f; } t; t.u = v;
    return t.f.x + t.f.y;
}
__device__ __forceinline__ ull dup2(float v) {
    ull r; asm("mov.b64 %0, {%1, %1};" : "=l"(r) : "f"(v)); return r;
}
union F4U { float4 f; ull u[2]; };

// MUFU-based transcendentals (validated R9-R13: rel_err stays ~1.05e-6)
__device__ __forceinline__ float sigf(float v) {
    return 1.f / (1.f + __expf(-v));
}
__device__ __forceinline__ float tanhfast(float x) {
    x = fminf(fmaxf(x, -10.f), 10.f);
    float a = __expf(2.f * x);
    return (a - 1.f) / (a + 1.f);
}

// ---------------- transpose_all (one launch) ----------------
#define TS0 (CDIM * NFEAT)
#define TS1 (CDIM * 768)
#define TS2 (CDIM * 768)
#define TS3 (CDIM * CDIM)
#define TS4 (CDIM * CDIM)
#define TTOT (TS0 + TS1 + TS2 + TS3 + TS4)
__global__ void transpose_all(const float* __restrict__ fd1_w, const float* __restrict__ c1_w,
                              const float* __restrict__ c2_w, const float* __restrict__ fd2_w,
                              const float* __restrict__ d1_w) {
    int idx = blockIdx.x * 256 + threadIdx.x;
    if (idx < TS0) { int n = idx / NFEAT, k = idx % NFEAT; g_fd1t[k * CDIM + n] = fd1_w[idx]; return; }
    idx -= TS0;
    if (idx < TS1) { int n = idx / 768, k = idx % 768; g_c1t[k * CDIM + n] = c1_w[idx]; return; }
    idx -= TS1;
    if (idx < TS2) { int n = idx / 768, k = idx % 768; g_c2t[k * CDIM + n] = c2_w[idx]; return; }
    idx -= TS2;
    if (idx < TS3) { int n = idx / CDIM, k = idx % CDIM; g_fd2t[k * CDIM + n] = fd2_w[idx]; return; }
    idx -= TS3;
    if (idx < TS4) { int j = idx / CDIM, k = idx % CDIM; g_d1t[k * CDIM + j] = d1_w[j * 296 + k]; }
}

// ---------------- fd1 ----------------
__global__ void fd1_kernel(const float* __restrict__ feat, const float* __restrict__ bias) {
    __shared__ float fs[NFEAT];
    int row = blockIdx.x;
    int tid = threadIdx.x;
    if (tid < NFEAT) fs[tid] = feat[row * NFEAT + tid];
    __syncthreads();
    float acc = bias[tid];
#pragma unroll
    for (int k = 0; k < NFEAT; k++)
        acc += g_fd1t[k * CDIM + tid] * fs[k];
    g_bufA[row * CDIM + tid] = tanhfast(acc);
}

// ---------------- fused conv1+conv2+fc+CP ----------------
#define CPAD 260
__global__ void __launch_bounds__(256, 1) cond_fused(
    const float* __restrict__ c1b, const float* __restrict__ c2b,
    const float* __restrict__ fcb, const float* __restrict__ d1b) {
    extern __shared__ float smf[];
    float* s_in = smf;                  // [22][260]
    float* s_m1 = smf + 22 * CPAD;      // [18][260] (reused for fc out [16][260])
    float* s_m2 = smf + 40 * CPAD;      // [16][260]

    int b = blockIdx.y;
    int t0 = blockIdx.x * 16;
    int tid = threadIdx.x;

#pragma unroll
    for (int r = 0; r < 22; r++) {
        int t = t0 + r;
        s_in[r * CPAD + tid] = (t < TFEAT) ? g_bufA[((size_t)b * TFEAT + t) * CDIM + tid] : 0.f;
    }
    __syncthreads();

    int tg = tid & 3;
    int c0 = (tid >> 2) * 4;

    // conv1 -> s_m1 rows 0..17
    {
        ull acc[5][2];
#pragma unroll
        for (int a = 0; a < 5; a++) { acc[a][0] = 0ull; acc[a][1] = 0ull; }
#pragma unroll 2
        for (int i = 0; i < CDIM; i++) {
#pragma unroll
            for (int j = 0; j < 3; j++) {
                F4U w; w.f = *reinterpret_cast<const float4*>(&g_c1t[(i * 3 + j) * CDIM + c0]);
#pragma unroll
                for (int a = 0; a < 5; a++) {
                    ull x2 = dup2(s_in[(tg + 4 * a + j) * CPAD + i]);
                    fma2(acc[a][0], w.u[0], x2);
                    fma2(acc[a][1], w.u[1], x2);
                }
            }
        }
        float4 bv = *reinterpret_cast<const float4*>(&c1b[c0]);
#pragma unroll
        for (int a = 0; a < 5; a++) {
            int r = tg + 4 * a;
            if (r < 18) {
                union { ull u; float2 f; } lo, hi;
                lo.u = acc[a][0]; hi.u = acc[a][1];
                float4 o;
                o.x = tanhfast(lo.f.x + bv.x); o.y = tanhfast(lo.f.y + bv.y);
                o.z = tanhfast(hi.f.x + bv.z); o.w = tanhfast(hi.f.y + bv.w);
                *reinterpret_cast<float4*>(&s_m1[r * CPAD + c0]) = o;
            }
        }
    }
    __syncthreads();

    // conv2 -> s_m2 rows 0..15
    {
        ull acc[4][2];
#pragma unroll
        for (int a = 0; a < 4; a++) { acc[a][0] = 0ull; acc[a][1] = 0ull; }
#pragma unroll 2
        for (int i = 0; i < CDIM; i++) {
#pragma unroll
            for (int j = 0; j < 3; j++) {
                F4U w; w.f = *reinterpret_cast<const float4*>(&g_c2t[(i * 3 + j) * CDIM + c0]);
#pragma unroll
                for (int a = 0; a < 4; a++) {
                    ull x2 = dup2(s_m1[(tg + 4 * a + j) * CPAD + i]);
                    fma2(acc[a][0], w.u[0], x2);
                    fma2(acc[a][1], w.u[1], x2);
                }
            }
        }
        float4 bv = *reinterpret_cast<const float4*>(&c2b[c0]);
#pragma unroll
        for (int a = 0; a < 4; a++) {
            int r = tg + 4 * a;
            union { ull u; float2 f; } lo, hi;
            lo.u = acc[a][0]; hi.u = acc[a][1];
            float4 o;
            o.x = tanhfast(lo.f.x + bv.x); o.y = tanhfast(lo.f.y + bv.y);
            o.z = tanhfast(hi.f.x + bv.z); o.w = tanhfast(hi.f.y + bv.w);
            *reinterpret_cast<float4*>(&s_m2[r * CPAD + c0]) = o;
        }
    }
    __syncthreads();

    // fc -> s_m1 rows 0..15 (cond stays in smem)
    {
        ull acc[4][2];
#pragma unroll
        for (int a = 0; a < 4; a++) { acc[a][0] = 0ull; acc[a][1] = 0ull; }
#pragma unroll 2
        for (int k = 0; k < CDIM; k++) {
            F4U w; w.f = *reinterpret_cast<const float4*>(&g_fd2t[k * CDIM + c0]);
#pragma unroll
            for (int a = 0; a < 4; a++) {
                ull x2 = dup2(s_m2[(tg + 4 * a) * CPAD + k]);
                fma2(acc[a][0], w.u[0], x2);
                fma2(acc[a][1], w.u[1], x2);
            }
        }
        float4 bv = *reinterpret_cast<const float4*>(&fcb[c0]);
#pragma unroll
        for (int a = 0; a < 4; a++) {
            int r = tg + 4 * a;
            union { ull u; float2 f; } lo, hi;
            lo.u = acc[a][0]; hi.u = acc[a][1];
            float4 o;
            o.x = tanhfast(lo.f.x + bv.x); o.y = tanhfast(lo.f.y + bv.y);
            o.z = tanhfast(hi.f.x + bv.z); o.w = tanhfast(hi.f.y + bv.w);
            *reinterpret_cast<float4*>(&s_m1[r * CPAD + c0]) = o;
        }
    }
    __syncthreads();

    // CP: cond @ d1t + d1_b -> g_cp (pre-activation)
    {
        ull acc[4][2];
#pragma unroll
        for (int a = 0; a < 4; a++) { acc[a][0] = 0ull; acc[a][1] = 0ull; }
#pragma unroll 2
        for (int k = 0; k < CDIM; k++) {
            F4U w; w.f = *reinterpret_cast<const float4*>(&g_d1t[k * CDIM + c0]);
#pragma unroll
            for (int a = 0; a < 4; a++) {
                ull x2 = dup2(s_m1[(tg + 4 * a) * CPAD + k]);
                fma2(acc[a][0], w.u[0], x2);
                fma2(acc[a][1], w.u[1], x2);
            }
        }
        float4 bv = *reinterpret_cast<const float4*>(&d1b[c0]);
#pragma unroll
        for (int a = 0; a < 4; a++) {
            int t = t0 + tg + 4 * a;
            if (t < 200) {
                union { ull u; float2 f; } lo, hi;
                lo.u = acc[a][0]; hi.u = acc[a][1];
                float4 o;
                o.x = lo.f.x + bv.x; o.y = lo.f.y + bv.y;
                o.z = hi.f.x + bv.z; o.w = hi.f.y + bv.w;
                *reinterpret_cast<float4*>(&g_cp[((size_t)b * 200 + t) * CDIM + c0]) = o;
            }
        }
    }
}

// ---------------- group barrier: red.release + acquire poll, padded counters ----------------
__device__ __forceinline__ void group_barrier(int grp, int target) {
    __syncthreads();
    if (threadIdx.x == 0) {
        int* addr = G_BAR(grp);
        asm volatile("red.release.gpu.global.add.s32 [%0], 1;"
                     :: "l"(addr) : "memory");
        int v;
        do {
            asm volatile("ld.acquire.gpu.global.s32 %0, [%1];"
                         : "=r"(v) : "l"(addr) : "memory");
        } while (v < target);
    }
    __syncthreads();
}

// ---------------- cooperative staging: 128 rows x 32-k chunk ----------------
struct Pre4 { float4 v[4]; };

__device__ __forceinline__ void ld4(Pre4& p, const float* __restrict__ base, int k0) {
#pragma unroll
    for (int i = 0; i < 4; i++) {
        int lin = threadIdx.x + i * NTHR;
        int row = lin >> 3, f4 = lin & 7;
        p.v[i] = __ldcg(reinterpret_cast<const float4*>(base + (size_t)row * CDIM + k0 + f4 * 4));
    }
}
__device__ __forceinline__ void st4(const Pre4& p, float* buf) {
#pragma unroll
    for (int i = 0; i < 4; i++) {
        int lin = threadIdx.x + i * NTHR;
        int row = lin >> 3, f4 = lin & 7;
        *reinterpret_cast<float4*>(buf + row * XSTR + f4 * 4) = p.v[i];
    }
}

// ---------------- persistent AR kernel: 4 groups x 32 slices, 256 thr ----------------
__global__ void __launch_bounds__(NTHR, 1) ar_kernel(
    const float* __restrict__ d1_w, const float* __restrict__ d2_w, const float* __restrict__ d2b,
    const float* __restrict__ w1i, const float* __restrict__ w1h,
    const float* __restrict__ b1i, const float* __restrict__ b1h,
    const float* __restrict__ w2i, const float* __restrict__ w2h,
    const float* __restrict__ b2i, const float* __restrict__ b2h,
    const float* __restrict__ w3i, const float* __restrict__ w3h,
    const float* __restrict__ b3i, const float* __restrict__ b3h,
    const float* __restrict__ ow,  const float* __restrict__ ob,
    const int* __restrict__ nbf,   float* __restrict__ out) {
    extern __shared__ float sm[];
    int tid = threadIdx.x;
    int s = blockIdx.x & (NSLICE - 1);
    int grp = blockIdx.x >> 5;
    int grow0 = grp * GROWS;

    // ---- resident weights ----
    for (int e = tid; e < 8 * CDIM; e += NTHR) {
        int r = e >> 8, k = e & 255;
        sm[O_WD2 + r * PDK + k] = d2_w[(s * 8 + r) * CDIM + k];
    }
    const float* wis[3] = {w1i, w2i, w3i};
    const float* whs[3] = {w1h, w2h, w3h};
    const float* bis[3] = {b1i, b2i, b3i};
    const float* bhs[3] = {b1h, b2h, b3h};
    for (int l = 0; l < 3; l++) {
        for (int e = tid; e < 24 * CDIM; e += NTHR) {
            int gr = e >> 8, k = e & 255;
            int g = gr >> 3, r = gr & 7;
            sm[O_GRU0 + l * GRU_STRIDE + gr * PDK + k] = wis[l][(g * CDIM + s * 8 + r) * CDIM + k];
            sm[O_GRU0 + l * GRU_STRIDE + 3 * 8 * PDK + gr * PDK + k] =
                whs[l][(g * CDIM + s * 8 + r) * CDIM + k];
        }
        if (tid < 24) {
            int g = tid >> 3, r = tid & 7;
            sm[O_BI0 + l * 48 + tid] = bis[l][g * CDIM + s * 8 + r];
            sm[O_BI0 + l * 48 + 24 + tid] = bhs[l][g * CDIM + s * 8 + r];
        }
    }
    if (s < 20) {
        for (int e = tid; e < 2 * CDIM; e += NTHR) {
            int r = e >> 8, k = e & 255;
            sm[O_WOW + r * PDK + k] = ow[(s * 2 + r) * CDIM + k];
        }
        if (tid < 2) sm[O_OB + tid] = ob[s * 2 + tid];
    }
    for (int e = tid; e < 8 * SUBD; e += NTHR) {
        int r = e / SUBD, q = e - r * SUBD;
        sm[O_D1P + r * 44 + q] = d1_w[(s * 8 + r) * 296 + 256 + q];
    }
    if (tid < 8) sm[O_BD2 + tid] = d2b[s * 8 + tid];
    __syncthreads();

    int c = tid & 7;
    int rq = tid >> 3;
    int scol = s * 8 + c;
    int ch_hold = scol >> 5;
    int kk_hold = scol & 31;

    float* xs = sm + O_XS;
    float* hs = sm + O_HS;

    int steps = nbf[0] * 4;
    int ostride = steps * SUBD;
    int bar_ep = 0;

    const float* CP = g_cp;
    float* t1g = g_t1 + (size_t)grow0 * CDIM;
    float* t2g = g_t2 + (size_t)grow0 * CDIM;
    float* pvg = G_PREV + (size_t)grow0 * SUBD;

    for (int st = 0; st < steps; st++) {
        int f = st >> 2;
        int p = st & 1;
        const float* h1o = G_H(p, 0) + (size_t)grow0 * CDIM;
        float*       h1n = G_H(p ^ 1, 0) + (size_t)grow0 * CDIM;
        const float* h2o = G_H(p, 1) + (size_t)grow0 * CDIM;
        float*       h2n = G_H(p ^ 1, 1) + (size_t)grow0 * CDIM;
        const float* h3o = G_H(p, 2) + (size_t)grow0 * CDIM;
        float*       h3n = G_H(p ^ 1, 2) + (size_t)grow0 * CDIM;

        // ========== d1: tanh(CP + prev @ Wp^T) ==========
        {
#pragma unroll
            for (int i = 0; i < 5; i++) {
                int lin = tid + i * NTHR;
                int row = lin / 10, f4 = lin - row * 10;
                *reinterpret_cast<float4*>(&xs[row * 44 + f4 * 4]) =
                    __ldcg(reinterpret_cast<const float4*>(&pvg[row * SUBD + f4 * 4]));
            }
            float cpv[4];
#pragma unroll
            for (int i = 0; i < 4; i++) {
                int row = grow0 + rq + 32 * i;
                cpv[i] = __ldcg(&CP[((size_t)row * 200 + f) * CDIM + scol]);
            }
            __syncthreads();
            ull A[4] = {0, 0, 0, 0};
            const float* wp = sm + O_D1P + c * 44;
#pragma unroll
            for (int k4 = 0; k4 < 10; k4++) {
                F4U W; W.f = *reinterpret_cast<const float4*>(wp + k4 * 4);
#pragma unroll
                for (int i = 0; i < 4; i++) {
                    F4U X; X.f = *reinterpret_cast<const float4*>(&xs[(rq + 32 * i) * 44 + k4 * 4]);
                    fma2(A[i], W.u[0], X.u[0]);
                    fma2(A[i], W.u[1], X.u[1]);
                }
            }
#pragma unroll
            for (int i = 0; i < 4; i++)
                __stcg(&t1g[(rq + 32 * i) * CDIM + scol], tanhfast(red2(A[i]) + cpv[i]));
        }
        group_barrier(grp, (++bar_ep) * NSLICE);

        // ========== d2 ==========
        {
            ull A[4] = {0, 0, 0, 0};
            const float* wp = sm + O_WD2 + c * PDK;
            Pre4 px;
            ld4(px, t1g, 0);
            st4(px, xs);
            __syncthreads();
            for (int ch = 0; ch < 8; ch++) {
                if (ch < 7) ld4(px, t1g, (ch + 1) * KCH);
                int k0 = ch * KCH;
#pragma unroll
                for (int k4 = 0; k4 < 8; k4++) {
                    F4U W; W.f = *reinterpret_cast<const float4*>(wp + k0 + k4 * 4);
#pragma unroll
                    for (int i = 0; i < 4; i++) {
                        F4U X; X.f = *reinterpret_cast<const float4*>(&xs[(rq + 32 * i) * XSTR + k4 * 4]);
                        fma2(A[i], W.u[0], X.u[0]);
                        fma2(A[i], W.u[1], X.u[1]);
                    }
                }
                if (ch < 7) {
                    __syncthreads();
                    st4(px, xs);
                    __syncthreads();
                }
            }
            float bb = sm[O_BD2 + c];
#pragma unroll
            for (int i = 0; i < 4; i++)
                __stcg(&t2g[(rq + 32 * i) * CDIM + scol], tanhfast(red2(A[i]) + bb));
        }
        group_barrier(grp, (++bar_ep) * NSLICE);

        // ========== 3 GRU layers ==========
        const float* xsrcs[3] = {t2g, h1n, h2n};
        const float* hsrcs[3] = {h1o, h2o, h3o};
        float*       hdsts[3] = {h1n, h2n, h3n};
        for (int gl = 0; gl < 3; gl++) {
            const float* xsrc = xsrcs[gl];
            const float* hsrc = hsrcs[gl];
            float*       hdst = hdsts[gl];

            const float* wb = sm + O_GRU0 + gl * GRU_STRIDE;
            const float* wr = wb + (0 * 8 + c) * PDK;
            const float* wz = wb + (1 * 8 + c) * PDK;
            const float* wn = wb + (2 * 8 + c) * PDK;
            const float* vr = wb + 3 * 8 * PDK + (0 * 8 + c) * PDK;
            const float* vz = wb + 3 * 8 * PDK + (1 * 8 + c) * PDK;
            const float* vn = wb + 3 * 8 * PDK + (2 * 8 + c) * PDK;

            ull Ar[4] = {0,0,0,0}, Az[4] = {0,0,0,0}, An[4] = {0,0,0,0};
            ull Br[4] = {0,0,0,0}, Bz[4] = {0,0,0,0}, Bn[4] = {0,0,0,0};
            float hold[4];

            Pre4 px, ph;
            ld4(px, xsrc, 0);
            ld4(ph, hsrc, 0);
            st4(px, xs);
            st4(ph, hs);
            __syncthreads();
            for (int ch = 0; ch < 8; ch++) {
                if (ch < 7) {
                    ld4(px, xsrc, (ch + 1) * KCH);
                    ld4(ph, hsrc, (ch + 1) * KCH);
                }
                int k0 = ch * KCH;
#pragma unroll
                for (int k4 = 0; k4 < 8; k4++) {
                    int gk = k0 + k4 * 4;
                    F4U Wr; Wr.f = *reinterpret_cast<const float4*>(wr + gk);
                    F4U Wz; Wz.f = *reinterpret_cast<const float4*>(wz + gk);
                    F4U Wn; Wn.f = *reinterpret_cast<const float4*>(wn + gk);
                    F4U Vr; Vr.f = *reinterpret_cast<const float4*>(vr + gk);
                    F4U Vz; Vz.f = *reinterpret_cast<const float4*>(vz + gk);
                    F4U Vn; Vn.f = *reinterpret_cast<const float4*>(vn + gk);
#pragma unroll
                    for (int i = 0; i < 4; i++) {
                        F4U X; X.f = *reinterpret_cast<const float4*>(&xs[(rq + 32 * i) * XSTR + k4 * 4]);
                        F4U H; H.f = *reinterpret_cast<const float4*>(&hs[(rq + 32 * i) * XSTR + k4 * 4]);
                        fma2(Ar[i], Wr.u[0], X.u[0]); fma2(Ar[i], Wr.u[1], X.u[1]);
                        fma2(Az[i], Wz.u[0], X.u[0]); fma2(Az[i], Wz.u[1], X.u[1]);
                        fma2(An[i], Wn.u[0], X.u[0]); fma2(An[i], Wn.u[1], X.u[1]);
                        fma2(Br[i], Vr.u[0], H.u[0]); fma2(Br[i], Vr.u[1], H.u[1]);
                        fma2(Bz[i], Vz.u[0], H.u[0]); fma2(Bz[i], Vz.u[1], H.u[1]);
                        fma2(Bn[i], Vn.u[0], H.u[0]); fma2(Bn[i], Vn.u[1], H.u[1]);
                    }
                }
                if (ch == ch_hold) {
#pragma unroll
                    for (int i = 0; i < 4; i++)
                        hold[i] = hs[(rq + 32 * i) * XSTR + kk_hold];
                }
                if (ch < 7) {
                    __syncthreads();
                    st4(px, xs);
                    st4(ph, hs);
                    __syncthreads();
                }
            }
            const float* bi = sm + O_BI0 + gl * 48;
            const float* bh = bi + 24;
            float bir = bi[c], biz = bi[8 + c], bin = bi[16 + c];
            float bhr = bh[c], bhz = bh[8 + c], bhn = bh[16 + c];
#pragma unroll
            for (int i = 0; i < 4; i++) {
                float r = sigf(red2(Ar[i]) + bir + red2(Br[i]) + bhr);
                float z = sigf(red2(Az[i]) + biz + red2(Bz[i]) + bhz);
                float n = tanhfast(red2(An[i]) + bin + r * (red2(Bn[i]) + bhn));
                __stcg(&hdst[(rq + 32 * i) * CDIM + scol], (1.f - z) * n + z * hold[i]);
            }
            group_barrier(grp, (++bar_ep) * NSLICE);
        }

        // ========== output layer: direct __ldcg reads, no staging/syncs ==========
        if (s < 20) {
            int lr = tid >> 1;
            int c2 = tid & 1;
            ull A = 0ull;
            const float* wp = sm + O_WOW + c2 * PDK;
            const float* hb = h3n + (size_t)lr * CDIM;
#pragma unroll 8
            for (int k4 = 0; k4 < 64; k4++) {
                F4U W; W.f = *reinterpret_cast<const float4*>(wp + k4 * 4);
                F4U X; X.f = __ldcg(reinterpret_cast<const float4*>(hb + k4 * 4));
                fma2(A, W.u[0], X.u[0]);
                fma2(A, W.u[1], X.u[1]);
            }
            float v = tanhfast(red2(A) + sm[O_OB + c2]);
            int Row = grow0 + lr;
            int oc = s * 2 + c2;
            out[(size_t)Row * ostride + st * SUBD + oc] = v;
            __stcg(&pvg[lr * SUBD + oc], v);
        }
        group_barrier(grp, (++bar_ep) * NSLICE);
    }
}

// ---------------- launcher ----------------
extern "C" void kernel_launch(void* const* d_in, const int* in_sizes, int n_in,
                              void* d_out, int out_size) {
    const float* feat   = (const float*)d_in[0];
    const float* fd1_w  = (const float*)d_in[1];
    const float* fd1_b  = (const float*)d_in[2];
    const float* c1_w   = (const float*)d_in[3];
    const float* c1_b   = (const float*)d_in[4];
    const float* c2_w   = (const float*)d_in[5];
    const float* c2_b   = (const float*)d_in[6];
    const float* fd2_w  = (const float*)d_in[7];
    const float* fd2_b  = (const float*)d_in[8];
    const float* d1_w   = (const float*)d_in[9];
    const float* d1_b   = (const float*)d_in[10];
    const float* d2_w   = (const float*)d_in[11];
    const float* d2_b   = (const float*)d_in[12];
    const float* g1_wih = (const float*)d_in[13];
    const float* g1_whh = (const float*)d_in[14];
    const float* g1_bih = (const float*)d_in[15];
    const float* g1_bhh = (const float*)d_in[16];
    const float* g2_wih = (const float*)d_in[17];
    const float* g2_whh = (const float*)d_in[18];
    const float* g2_bih = (const float*)d_in[19];
    const float* g2_bhh = (const float*)d_in[20];
    const float* g3_wih = (const float*)d_in[21];
    const float* g3_whh = (const float*)d_in[22];
    const float* g3_bih = (const float*)d_in[23];
    const float* g3_bhh = (const float*)d_in[24];
    const float* ow     = (const float*)d_in[25];
    const float* ob     = (const float*)d_in[26];
    const int*   nbf    = (const int*)d_in[27];
    float* out = (float*)d_out;

    float* pState;
    cudaGetSymbolAddress((void**)&pState, g_state);

    static bool attr_set = false;
    if (!attr_set) {
        cudaFuncSetAttribute(cond_fused, cudaFuncAttributeMaxDynamicSharedMemorySize,
                             56 * CPAD * 4);
        cudaFuncSetAttribute(ar_kernel, cudaFuncAttributeMaxDynamicSharedMemorySize, SM_BYTES);
        attr_set = true;
    }

    cudaMemsetAsync(pState, 0, STATE_TOT * sizeof(float));
    transpose_all<<<(TTOT + 255) / 256, 256>>>(fd1_w, c1_w, c2_w, fd2_w, d1_w);
    fd1_kernel<<<BATCH * TFEAT, 256>>>(feat, fd1_b);
    cond_fused<<<dim3(13, BATCH), 256, 56 * CPAD * 4>>>(c1_b, c2_b, fd2_b, d1_b);
    ar_kernel<<<NCTA, NTHR, SM_BYTES>>>(
        d1_w, d2_w, d2_b,
        g1_wih, g1_whh, g1_bih, g1_bhh,
        g2_wih, g2_whh, g2_bih, g2_bhh,
        g3_wih, g3_whh, g3_bih, g3_bhh,
        ow, ob, nbf, out);
}

// round 15
// speedup vs baseline: 1.0271x; 1.0271x over previous
#include <cuda_runtime.h>
#include <math.h>

typedef unsigned long long ull;

#define BATCH 512
#define TFEAT 204
#define NFEAT 20
#define CDIM  256
#define SUBD  40
#define NSLICE 32
#define NGRP   4
#define GROWS  128
#define NCTA   128
#define NTHR   256
#define KCH    32
#define XSTR   36

// ---------------- device globals ----------------
__device__ float g_bufA[BATCH * TFEAT * CDIM];   // fd1 out
__device__ float g_cp[BATCH * 200 * CDIM];       // CP = cond @ d1_w[:, :256]^T + d1_b

__device__ float g_fd1t[NFEAT * CDIM];
__device__ float g_c1t[768 * CDIM];
__device__ float g_c2t[768 * CDIM];
__device__ float g_fd2t[CDIM * CDIM];
__device__ float g_d1t[CDIM * CDIM];             // transposed first-256-k of d1_w

__device__ float g_t1[BATCH * CDIM];
__device__ float g_t2[BATCH * CDIM];

// zeroed state: h ping-pong(6 planes) + prev + padded barrier counters (one memset)
#define STATE_H     0
#define STATE_PREV  (6 * BATCH * CDIM)
#define STATE_BAR   (STATE_PREV + BATCH * SUBD)
#define STATE_TOT   (STATE_BAR + NGRP * 32)
__device__ float g_state[STATE_TOT];
#define G_H(p, l)   (g_state + ((p) * 3 + (l)) * (BATCH * CDIM))
#define G_PREV      (g_state + STATE_PREV)
#define G_BAR(grp)  ((int*)(g_state + STATE_BAR) + (grp) * 32)   // 128B apart

// ---------------- smem layout for AR (floats) ----------------
#define PDK 260
#define O_WD2  0
#define O_GRU0 2080
#define GRU_STRIDE 12480
#define O_WOW  (O_GRU0 + 3 * GRU_STRIDE)  // 39520
#define O_D1P  (O_WOW + 520)              // [8][44]
#define O_BD2  (O_D1P + 352)
#define O_BI0  (O_BD2 + 8)
#define O_OB   (O_BI0 + 144)
#define O_XS   40548
#define O_HS   (O_XS + 4608)
#define SM_FLOATS (O_HS + 4608)
#define SM_BYTES  (SM_FLOATS * 4)

// ---------------- f32x2 helpers ----------------
__device__ __forceinline__ void fma2(ull& d, ull a, ull b) {
    asm("fma.rn.f32x2 %0, %1, %2, %0;" : "+l"(d) : "l"(a), "l"(b));
}
__device__ __forceinline__ float red2(ull v) {
    union { ull u; float2 f; } t; t.u = v;
    return t.f.x + t.f.y;
}
__device__ __forceinline__ ull dup2(float v) {
    ull r; asm("mov.b64 %0, {%1, %1};" : "=l"(r) : "f"(v)); return r;
}
union F4U { float4 f; ull u[2]; };

// MUFU-based transcendentals (validated R9-R14: rel_err stays ~1.06e-6)
__device__ __forceinline__ float sigf(float v) {
    return 1.f / (1.f + __expf(-v));
}
__device__ __forceinline__ float tanhfast(float x) {
    x = fminf(fmaxf(x, -10.f), 10.f);
    float a = __expf(2.f * x);
    return (a - 1.f) / (a + 1.f);
}

// ---------------- transpose_all (one launch) ----------------
#define TS0 (CDIM * NFEAT)
#define TS1 (CDIM * 768)
#define TS2 (CDIM * 768)
#define TS3 (CDIM * CDIM)
#define TS4 (CDIM * CDIM)
#define TTOT (TS0 + TS1 + TS2 + TS3 + TS4)
__global__ void transpose_all(const float* __restrict__ fd1_w, const float* __restrict__ c1_w,
                              const float* __restrict__ c2_w, const float* __restrict__ fd2_w,
                              const float* __restrict__ d1_w) {
    int idx = blockIdx.x * 256 + threadIdx.x;
    if (idx < TS0) { int n = idx / NFEAT, k = idx % NFEAT; g_fd1t[k * CDIM + n] = fd1_w[idx]; return; }
    idx -= TS0;
    if (idx < TS1) { int n = idx / 768, k = idx % 768; g_c1t[k * CDIM + n] = c1_w[idx]; return; }
    idx -= TS1;
    if (idx < TS2) { int n = idx / 768, k = idx % 768; g_c2t[k * CDIM + n] = c2_w[idx]; return; }
    idx -= TS2;
    if (idx < TS3) { int n = idx / CDIM, k = idx % CDIM; g_fd2t[k * CDIM + n] = fd2_w[idx]; return; }
    idx -= TS3;
    if (idx < TS4) { int j = idx / CDIM, k = idx % CDIM; g_d1t[k * CDIM + j] = d1_w[j * 296 + k]; }
}

// ---------------- fd1 ----------------
__global__ void fd1_kernel(const float* __restrict__ feat, const float* __restrict__ bias) {
    __shared__ float fs[NFEAT];
    int row = blockIdx.x;
    int tid = threadIdx.x;
    if (tid < NFEAT) fs[tid] = feat[row * NFEAT + tid];
    __syncthreads();
    float acc = bias[tid];
#pragma unroll
    for (int k = 0; k < NFEAT; k++)
        acc += g_fd1t[k * CDIM + tid] * fs[k];
    g_bufA[row * CDIM + tid] = tanhfast(acc);
}

// ---------------- fused conv1+conv2+fc+CP ----------------
#define CPAD 260
__global__ void __launch_bounds__(256, 1) cond_fused(
    const float* __restrict__ c1b, const float* __restrict__ c2b,
    const float* __restrict__ fcb, const float* __restrict__ d1b) {
    extern __shared__ float smf[];
    float* s_in = smf;                  // [22][260]
    float* s_m1 = smf + 22 * CPAD;      // [18][260] (reused for fc out [16][260])
    float* s_m2 = smf + 40 * CPAD;      // [16][260]

    int b = blockIdx.y;
    int t0 = blockIdx.x * 16;
    int tid = threadIdx.x;

#pragma unroll
    for (int r = 0; r < 22; r++) {
        int t = t0 + r;
        s_in[r * CPAD + tid] = (t < TFEAT) ? g_bufA[((size_t)b * TFEAT + t) * CDIM + tid] : 0.f;
    }
    __syncthreads();

    int tg = tid & 3;
    int c0 = (tid >> 2) * 4;

    // conv1 -> s_m1 rows 0..17
    {
        ull acc[5][2];
#pragma unroll
        for (int a = 0; a < 5; a++) { acc[a][0] = 0ull; acc[a][1] = 0ull; }
#pragma unroll 2
        for (int i = 0; i < CDIM; i++) {
#pragma unroll
            for (int j = 0; j < 3; j++) {
                F4U w; w.f = *reinterpret_cast<const float4*>(&g_c1t[(i * 3 + j) * CDIM + c0]);
#pragma unroll
                for (int a = 0; a < 5; a++) {
                    ull x2 = dup2(s_in[(tg + 4 * a + j) * CPAD + i]);
                    fma2(acc[a][0], w.u[0], x2);
                    fma2(acc[a][1], w.u[1], x2);
                }
            }
        }
        float4 bv = *reinterpret_cast<const float4*>(&c1b[c0]);
#pragma unroll
        for (int a = 0; a < 5; a++) {
            int r = tg + 4 * a;
            if (r < 18) {
                union { ull u; float2 f; } lo, hi;
                lo.u = acc[a][0]; hi.u = acc[a][1];
                float4 o;
                o.x = tanhfast(lo.f.x + bv.x); o.y = tanhfast(lo.f.y + bv.y);
                o.z = tanhfast(hi.f.x + bv.z); o.w = tanhfast(hi.f.y + bv.w);
                *reinterpret_cast<float4*>(&s_m1[r * CPAD + c0]) = o;
            }
        }
    }
    __syncthreads();

    // conv2 -> s_m2 rows 0..15
    {
        ull acc[4][2];
#pragma unroll
        for (int a = 0; a < 4; a++) { acc[a][0] = 0ull; acc[a][1] = 0ull; }
#pragma unroll 2
        for (int i = 0; i < CDIM; i++) {
#pragma unroll
            for (int j = 0; j < 3; j++) {
                F4U w; w.f = *reinterpret_cast<const float4*>(&g_c2t[(i * 3 + j) * CDIM + c0]);
#pragma unroll
                for (int a = 0; a < 4; a++) {
                    ull x2 = dup2(s_m1[(tg + 4 * a + j) * CPAD + i]);
                    fma2(acc[a][0], w.u[0], x2);
                    fma2(acc[a][1], w.u[1], x2);
                }
            }
        }
        float4 bv = *reinterpret_cast<const float4*>(&c2b[c0]);
#pragma unroll
        for (int a = 0; a < 4; a++) {
            int r = tg + 4 * a;
            union { ull u; float2 f; } lo, hi;
            lo.u = acc[a][0]; hi.u = acc[a][1];
            float4 o;
            o.x = tanhfast(lo.f.x + bv.x); o.y = tanhfast(lo.f.y + bv.y);
            o.z = tanhfast(hi.f.x + bv.z); o.w = tanhfast(hi.f.y + bv.w);
            *reinterpret_cast<float4*>(&s_m2[r * CPAD + c0]) = o;
        }
    }
    __syncthreads();

    // fc -> s_m1 rows 0..15 (cond stays in smem)
    {
        ull acc[4][2];
#pragma unroll
        for (int a = 0; a < 4; a++) { acc[a][0] = 0ull; acc[a][1] = 0ull; }
#pragma unroll 2
        for (int k = 0; k < CDIM; k++) {
            F4U w; w.f = *reinterpret_cast<const float4*>(&g_fd2t[k * CDIM + c0]);
#pragma unroll
            for (int a = 0; a < 4; a++) {
                ull x2 = dup2(s_m2[(tg + 4 * a) * CPAD + k]);
                fma2(acc[a][0], w.u[0], x2);
                fma2(acc[a][1], w.u[1], x2);
            }
        }
        float4 bv = *reinterpret_cast<const float4*>(&fcb[c0]);
#pragma unroll
        for (int a = 0; a < 4; a++) {
            int r = tg + 4 * a;
            union { ull u; float2 f; } lo, hi;
            lo.u = acc[a][0]; hi.u = acc[a][1];
            float4 o;
            o.x = tanhfast(lo.f.x + bv.x); o.y = tanhfast(lo.f.y + bv.y);
            o.z = tanhfast(hi.f.x + bv.z); o.w = tanhfast(hi.f.y + bv.w);
            *reinterpret_cast<float4*>(&s_m1[r * CPAD + c0]) = o;
        }
    }
    __syncthreads();

    // CP: cond @ d1t + d1_b -> g_cp (pre-activation)
    {
        ull acc[4][2];
#pragma unroll
        for (int a = 0; a < 4; a++) { acc[a][0] = 0ull; acc[a][1] = 0ull; }
#pragma unroll 2
        for (int k = 0; k < CDIM; k++) {
            F4U w; w.f = *reinterpret_cast<const float4*>(&g_d1t[k * CDIM + c0]);
#pragma unroll
            for (int a = 0; a < 4; a++) {
                ull x2 = dup2(s_m1[(tg + 4 * a) * CPAD + k]);
                fma2(acc[a][0], w.u[0], x2);
                fma2(acc[a][1], w.u[1], x2);
            }
        }
        float4 bv = *reinterpret_cast<const float4*>(&d1b[c0]);
#pragma unroll
        for (int a = 0; a < 4; a++) {
            int t = t0 + tg + 4 * a;
            if (t < 200) {
                union { ull u; float2 f; } lo, hi;
                lo.u = acc[a][0]; hi.u = acc[a][1];
                float4 o;
                o.x = lo.f.x + bv.x; o.y = lo.f.y + bv.y;
                o.z = hi.f.x + bv.z; o.w = hi.f.y + bv.w;
                *reinterpret_cast<float4*>(&g_cp[((size_t)b * 200 + t) * CDIM + c0]) = o;
            }
        }
    }
}

// ---------------- group barrier: red.release + acquire poll, padded counters ----------------
__device__ __forceinline__ void group_barrier(int grp, int target) {
    __syncthreads();
    if (threadIdx.x == 0) {
        int* addr = G_BAR(grp);
        asm volatile("red.release.gpu.global.add.s32 [%0], 1;"
                     :: "l"(addr) : "memory");
        int v;
        do {
            asm volatile("ld.acquire.gpu.global.s32 %0, [%1];"
                         : "=r"(v) : "l"(addr) : "memory");
        } while (v < target);
    }
    __syncthreads();
}

// ---------------- cooperative staging: 128 rows x 32-k chunk ----------------
struct Pre4 { float4 v[4]; };

__device__ __forceinline__ void ld4(Pre4& p, const float* __restrict__ base, int k0) {
#pragma unroll
    for (int i = 0; i < 4; i++) {
        int lin = threadIdx.x + i * NTHR;
        int row = lin >> 3, f4 = lin & 7;
        p.v[i] = __ldcg(reinterpret_cast<const float4*>(base + (size_t)row * CDIM + k0 + f4 * 4));
    }
}
__device__ __forceinline__ void st4(const Pre4& p, float* buf) {
#pragma unroll
    for (int i = 0; i < 4; i++) {
        int lin = threadIdx.x + i * NTHR;
        int row = lin >> 3, f4 = lin & 7;
        *reinterpret_cast<float4*>(buf + row * XSTR + f4 * 4) = p.v[i];
    }
}

// ---------------- persistent AR kernel: 4 groups x 32 slices, 256 thr ----------------
__global__ void __launch_bounds__(NTHR, 1) ar_kernel(
    const float* __restrict__ d1_w, const float* __restrict__ d2_w, const float* __restrict__ d2b,
    const float* __restrict__ w1i, const float* __restrict__ w1h,
    const float* __restrict__ b1i, const float* __restrict__ b1h,
    const float* __restrict__ w2i, const float* __restrict__ w2h,
    const float* __restrict__ b2i, const float* __restrict__ b2h,
    const float* __restrict__ w3i, const float* __restrict__ w3h,
    const float* __restrict__ b3i, const float* __restrict__ b3h,
    const float* __restrict__ ow,  const float* __restrict__ ob,
    const int* __restrict__ nbf,   float* __restrict__ out) {
    extern __shared__ float sm[];
    int tid = threadIdx.x;
    int s = blockIdx.x & (NSLICE - 1);
    int grp = blockIdx.x >> 5;
    int grow0 = grp * GROWS;

    // ---- resident weights ----
    for (int e = tid; e < 8 * CDIM; e += NTHR) {
        int r = e >> 8, k = e & 255;
        sm[O_WD2 + r * PDK + k] = d2_w[(s * 8 + r) * CDIM + k];
    }
    const float* wis[3] = {w1i, w2i, w3i};
    const float* whs[3] = {w1h, w2h, w3h};
    const float* bis[3] = {b1i, b2i, b3i};
    const float* bhs[3] = {b1h, b2h, b3h};
    for (int l = 0; l < 3; l++) {
        for (int e = tid; e < 24 * CDIM; e += NTHR) {
            int gr = e >> 8, k = e & 255;
            int g = gr >> 3, r = gr & 7;
            sm[O_GRU0 + l * GRU_STRIDE + gr * PDK + k] = wis[l][(g * CDIM + s * 8 + r) * CDIM + k];
            sm[O_GRU0 + l * GRU_STRIDE + 3 * 8 * PDK + gr * PDK + k] =
                whs[l][(g * CDIM + s * 8 + r) * CDIM + k];
        }
        if (tid < 24) {
            int g = tid >> 3, r = tid & 7;
            sm[O_BI0 + l * 48 + tid] = bis[l][g * CDIM + s * 8 + r];
            sm[O_BI0 + l * 48 + 24 + tid] = bhs[l][g * CDIM + s * 8 + r];
        }
    }
    if (s < 20) {
        for (int e = tid; e < 2 * CDIM; e += NTHR) {
            int r = e >> 8, k = e & 255;
            sm[O_WOW + r * PDK + k] = ow[(s * 2 + r) * CDIM + k];
        }
        if (tid < 2) sm[O_OB + tid] = ob[s * 2 + tid];
    }
    for (int e = tid; e < 8 * SUBD; e += NTHR) {
        int r = e / SUBD, q = e - r * SUBD;
        sm[O_D1P + r * 44 + q] = d1_w[(s * 8 + r) * 296 + 256 + q];
    }
    if (tid < 8) sm[O_BD2 + tid] = d2b[s * 8 + tid];
    __syncthreads();

    int c = tid & 7;
    int rq = tid >> 3;
    int scol = s * 8 + c;
    int ch_hold = scol >> 5;
    int kk_hold = scol & 31;

    float* xs = sm + O_XS;
    float* hs = sm + O_HS;

    int steps = nbf[0] * 4;
    int ostride = steps * SUBD;
    int bar_ep = 0;

    const float* CP = g_cp;
    float* t1g = g_t1 + (size_t)grow0 * CDIM;
    float* t2g = g_t2 + (size_t)grow0 * CDIM;
    float* pvg = G_PREV + (size_t)grow0 * SUBD;

    for (int st = 0; st < steps; st++) {
        int f = st >> 2;
        int p = st & 1;
        const float* h1o = G_H(p, 0) + (size_t)grow0 * CDIM;
        float*       h1n = G_H(p ^ 1, 0) + (size_t)grow0 * CDIM;
        const float* h2o = G_H(p, 1) + (size_t)grow0 * CDIM;
        float*       h2n = G_H(p ^ 1, 1) + (size_t)grow0 * CDIM;
        const float* h3o = G_H(p, 2) + (size_t)grow0 * CDIM;
        float*       h3n = G_H(p ^ 1, 2) + (size_t)grow0 * CDIM;

        // ========== d1: tanh(CP + prev @ Wp^T) ==========
        {
#pragma unroll
            for (int i = 0; i < 5; i++) {
                int lin = tid + i * NTHR;
                int row = lin / 10, f4 = lin - row * 10;
                *reinterpret_cast<float4*>(&xs[row * 44 + f4 * 4]) =
                    __ldcg(reinterpret_cast<const float4*>(&pvg[row * SUBD + f4 * 4]));
            }
            float cpv[4];
#pragma unroll
            for (int i = 0; i < 4; i++) {
                int row = grow0 + rq + 32 * i;
                cpv[i] = __ldcg(&CP[((size_t)row * 200 + f) * CDIM + scol]);
            }
            __syncthreads();
            ull A[4] = {0, 0, 0, 0};
            const float* wp = sm + O_D1P + c * 44;
#pragma unroll
            for (int k4 = 0; k4 < 10; k4++) {
                F4U W; W.f = *reinterpret_cast<const float4*>(wp + k4 * 4);
#pragma unroll
                for (int i = 0; i < 4; i++) {
                    F4U X; X.f = *reinterpret_cast<const float4*>(&xs[(rq + 32 * i) * 44 + k4 * 4]);
                    fma2(A[i], W.u[0], X.u[0]);
                    fma2(A[i], W.u[1], X.u[1]);
                }
            }
#pragma unroll
            for (int i = 0; i < 4; i++)
                __stcg(&t1g[(rq + 32 * i) * CDIM + scol], tanhfast(red2(A[i]) + cpv[i]));
        }
        group_barrier(grp, (++bar_ep) * NSLICE);

        // ========== d2 ==========
        {
            ull A[4] = {0, 0, 0, 0};
            const float* wp = sm + O_WD2 + c * PDK;
            Pre4 px;
            ld4(px, t1g, 0);
            st4(px, xs);
            __syncthreads();
            for (int ch = 0; ch < 8; ch++) {
                if (ch < 7) ld4(px, t1g, (ch + 1) * KCH);
                int k0 = ch * KCH;
#pragma unroll
                for (int k4 = 0; k4 < 8; k4++) {
                    F4U W; W.f = *reinterpret_cast<const float4*>(wp + k0 + k4 * 4);
#pragma unroll
                    for (int i = 0; i < 4; i++) {
                        F4U X; X.f = *reinterpret_cast<const float4*>(&xs[(rq + 32 * i) * XSTR + k4 * 4]);
                        fma2(A[i], W.u[0], X.u[0]);
                        fma2(A[i], W.u[1], X.u[1]);
                    }
                }
                if (ch < 7) {
                    __syncthreads();
                    st4(px, xs);
                    __syncthreads();
                }
            }
            float bb = sm[O_BD2 + c];
#pragma unroll
            for (int i = 0; i < 4; i++)
                __stcg(&t2g[(rq + 32 * i) * CDIM + scol], tanhfast(red2(A[i]) + bb));
        }
        group_barrier(grp, (++bar_ep) * NSLICE);

        // ========== 3 GRU layers ==========
        const float* xsrcs[3] = {t2g, h1n, h2n};
        const float* hsrcs[3] = {h1o, h2o, h3o};
        float*       hdsts[3] = {h1n, h2n, h3n};
        for (int gl = 0; gl < 3; gl++) {
            const float* xsrc = xsrcs[gl];
            const float* hsrc = hsrcs[gl];
            float*       hdst = hdsts[gl];

            const float* wb = sm + O_GRU0 + gl * GRU_STRIDE;
            const float* wr = wb + (0 * 8 + c) * PDK;
            const float* wz = wb + (1 * 8 + c) * PDK;
            const float* wn = wb + (2 * 8 + c) * PDK;
            const float* vr = wb + 3 * 8 * PDK + (0 * 8 + c) * PDK;
            const float* vz = wb + 3 * 8 * PDK + (1 * 8 + c) * PDK;
            const float* vn = wb + 3 * 8 * PDK + (2 * 8 + c) * PDK;

            ull Ar[4] = {0,0,0,0}, Az[4] = {0,0,0,0}, An[4] = {0,0,0,0};
            ull Br[4] = {0,0,0,0}, Bz[4] = {0,0,0,0}, Bn[4] = {0,0,0,0};
            float hold[4];

            Pre4 px, ph;
            ld4(px, xsrc, 0);
            ld4(ph, hsrc, 0);
            st4(px, xs);
            st4(ph, hs);
            __syncthreads();
            for (int ch = 0; ch < 8; ch++) {
                if (ch < 7) {
                    ld4(px, xsrc, (ch + 1) * KCH);
                    ld4(ph, hsrc, (ch + 1) * KCH);
                }
                int k0 = ch * KCH;
#pragma unroll
                for (int k4 = 0; k4 < 8; k4++) {
                    int gk = k0 + k4 * 4;
                    F4U Wr; Wr.f = *reinterpret_cast<const float4*>(wr + gk);
                    F4U Wz; Wz.f = *reinterpret_cast<const float4*>(wz + gk);
                    F4U Wn; Wn.f = *reinterpret_cast<const float4*>(wn + gk);
                    F4U Vr; Vr.f = *reinterpret_cast<const float4*>(vr + gk);
                    F4U Vz; Vz.f = *reinterpret_cast<const float4*>(vz + gk);
                    F4U Vn; Vn.f = *reinterpret_cast<const float4*>(vn + gk);
#pragma unroll
                    for (int i = 0; i < 4; i++) {
                        F4U X; X.f = *reinterpret_cast<const float4*>(&xs[(rq + 32 * i) * XSTR + k4 * 4]);
                        F4U H; H.f = *reinterpret_cast<const float4*>(&hs[(rq + 32 * i) * XSTR + k4 * 4]);
                        fma2(Ar[i], Wr.u[0], X.u[0]); fma2(Ar[i], Wr.u[1], X.u[1]);
                        fma2(Az[i], Wz.u[0], X.u[0]); fma2(Az[i], Wz.u[1], X.u[1]);
                        fma2(An[i], Wn.u[0], X.u[0]); fma2(An[i], Wn.u[1], X.u[1]);
                        fma2(Br[i], Vr.u[0], H.u[0]); fma2(Br[i], Vr.u[1], H.u[1]);
                        fma2(Bz[i], Vz.u[0], H.u[0]); fma2(Bz[i], Vz.u[1], H.u[1]);
                        fma2(Bn[i], Vn.u[0], H.u[0]); fma2(Bn[i], Vn.u[1], H.u[1]);
                    }
                }
                if (ch == ch_hold) {
#pragma unroll
                    for (int i = 0; i < 4; i++)
                        hold[i] = hs[(rq + 32 * i) * XSTR + kk_hold];
                }
                if (ch < 7) {
                    __syncthreads();
                    st4(px, xs);
                    st4(ph, hs);
                    __syncthreads();
                }
            }
            const float* bi = sm + O_BI0 + gl * 48;
            const float* bh = bi + 24;
            float bir = bi[c], biz = bi[8 + c], bin = bi[16 + c];
            float bhr = bh[c], bhz = bh[8 + c], bhn = bh[16 + c];
#pragma unroll
            for (int i = 0; i < 4; i++) {
                float r = sigf(red2(Ar[i]) + bir + red2(Br[i]) + bhr);
                float z = sigf(red2(Az[i]) + biz + red2(Bz[i]) + bhz);
                float n = tanhfast(red2(An[i]) + bin + r * (red2(Bn[i]) + bhn));
                __stcg(&hdst[(rq + 32 * i) * CDIM + scol], (1.f - z) * n + z * hold[i]);
            }
            group_barrier(grp, (++bar_ep) * NSLICE);
        }

        // ========== output layer (slices 0..19: 2 cols x 128 rows, staged) ==========
        if (s < 20) {
            int lr = tid >> 1;
            int c2 = tid & 1;
            ull A = 0ull;
            const float* wp = sm + O_WOW + c2 * PDK;
            Pre4 ph;
            ld4(ph, h3n, 0);
            st4(ph, xs);
            __syncthreads();
            for (int ch = 0; ch < 8; ch++) {
                if (ch < 7) ld4(ph, h3n, (ch + 1) * KCH);
                int k0 = ch * KCH;
#pragma unroll
                for (int k4 = 0; k4 < 8; k4++) {
                    F4U W; W.f = *reinterpret_cast<const float4*>(wp + k0 + k4 * 4);
                    F4U X; X.f = *reinterpret_cast<const float4*>(&xs[lr * XSTR + k4 * 4]);
                    fma2(A, W.u[0], X.u[0]);
                    fma2(A, W.u[1], X.u[1]);
                }
                if (ch < 7) {
                    __syncthreads();
                    st4(ph, xs);
                    __syncthreads();
                }
            }
            float v = tanhfast(red2(A) + sm[O_OB + c2]);
            int Row = grow0 + lr;
            int oc = s * 2 + c2;
            out[(size_t)Row * ostride + st * SUBD + oc] = v;
            __stcg(&pvg[lr * SUBD + oc], v);
        }
        group_barrier(grp, (++bar_ep) * NSLICE);
    }
}

// ---------------- launcher ----------------
extern "C" void kernel_launch(void* const* d_in, const int* in_sizes, int n_in,
                              void* d_out, int out_size) {
    const float* feat   = (const float*)d_in[0];
    const float* fd1_w  = (const float*)d_in[1];
    const float* fd1_b  = (const float*)d_in[2];
    const float* c1_w   = (const float*)d_in[3];
    const float* c1_b   = (const float*)d_in[4];
    const float* c2_w   = (const float*)d_in[5];
    const float* c2_b   = (const float*)d_in[6];
    const float* fd2_w  = (const float*)d_in[7];
    const float* fd2_b  = (const float*)d_in[8];
    const float* d1_w   = (const float*)d_in[9];
    const float* d1_b   = (const float*)d_in[10];
    const float* d2_w   = (const float*)d_in[11];
    const float* d2_b   = (const float*)d_in[12];
    const float* g1_wih = (const float*)d_in[13];
    const float* g1_whh = (const float*)d_in[14];
    const float* g1_bih = (const float*)d_in[15];
    const float* g1_bhh = (const float*)d_in[16];
    const float* g2_wih = (const float*)d_in[17];
    const float* g2_whh = (const float*)d_in[18];
    const float* g2_bih = (const float*)d_in[19];
    const float* g2_bhh = (const float*)d_in[20];
    const float* g3_wih = (const float*)d_in[21];
    const float* g3_whh = (const float*)d_in[22];
    const float* g3_bih = (const float*)d_in[23];
    const float* g3_bhh = (const float*)d_in[24];
    const float* ow     = (const float*)d_in[25];
    const float* ob     = (const float*)d_in[26];
    const int*   nbf    = (const int*)d_in[27];
    float* out = (float*)d_out;

    float* pState;
    cudaGetSymbolAddress((void**)&pState, g_state);

    static bool attr_set = false;
    if (!attr_set) {
        cudaFuncSetAttribute(cond_fused, cudaFuncAttributeMaxDynamicSharedMemorySize,
                             56 * CPAD * 4);
        cudaFuncSetAttribute(ar_kernel, cudaFuncAttributeMaxDynamicSharedMemorySize, SM_BYTES);
        attr_set = true;
    }

    cudaMemsetAsync(pState, 0, STATE_TOT * sizeof(float));
    transpose_all<<<(TTOT + 255) / 256, 256>>>(fd1_w, c1_w, c2_w, fd2_w, d1_w);
    fd1_kernel<<<BATCH * TFEAT, 256>>>(feat, fd1_b);
    cond_fused<<<dim3(13, BATCH), 256, 56 * CPAD * 4>>>(c1_b, c2_b, fd2_b, d1_b);
    ar_kernel<<<NCTA, NTHR, SM_BYTES>>>(
        d1_w, d2_w, d2_b,
        g1_wih, g1_whh, g1_bih, g1_bhh,
        g2_wih, g2_whh, g2_bih, g2_bhh,
        g3_wih, g3_whh, g3_bih, g3_bhh,
        ow, ob, nbf, out);
}

// round 16
// speedup vs baseline: 1.0650x; 1.0369x over previous
#include <cuda_runtime.h>
#include <math.h>

typedef unsigned long long ull;

#define BATCH 512
#define TFEAT 204
#define NFEAT 20
#define CDIM  256
#define SUBD  40
#define NSLICE 32
#define NGRP   4
#define GROWS  128
#define NCTA   128
#define NTHR   256
#define KCH    32
#define XSTR   36

// ---------------- device globals ----------------
__device__ float g_bufA[BATCH * TFEAT * CDIM];   // fd1 out
__device__ float g_cp[BATCH * 200 * CDIM];       // CP = cond @ d1_w[:, :256]^T + d1_b

__device__ float g_fd1t[NFEAT * CDIM];
__device__ float g_c1t[768 * CDIM];
__device__ float g_c2t[768 * CDIM];
__device__ float g_fd2t[CDIM * CDIM];
__device__ float g_d1t[CDIM * CDIM];             // transposed first-256-k of d1_w

__device__ float g_t1[BATCH * CDIM];
__device__ float g_t2[BATCH * CDIM];

// zeroed state: h ping-pong(6 planes) + prev + padded barrier counters (one memset)
#define STATE_H     0
#define STATE_PREV  (6 * BATCH * CDIM)
#define STATE_BAR   (STATE_PREV + BATCH * SUBD)
#define STATE_TOT   (STATE_BAR + NGRP * 32)
__device__ float g_state[STATE_TOT];
#define G_H(p, l)   (g_state + ((p) * 3 + (l)) * (BATCH * CDIM))
#define G_PREV      (g_state + STATE_PREV)
#define G_BAR(grp)  ((int*)(g_state + STATE_BAR) + (grp) * 32)   // 128B apart

// ---------------- smem layout for AR (floats) ----------------
#define PDK 260
#define O_WD2  0
#define O_GRU0 2080
#define GRU_STRIDE 12480
#define O_WOW  (O_GRU0 + 3 * GRU_STRIDE)  // 39520
#define O_D1P  (O_WOW + 520)              // [8][44]
#define O_BD2  (O_D1P + 352)
#define O_BI0  (O_BD2 + 8)
#define O_OB   (O_BI0 + 144)
#define O_XS   40548
#define O_HS   (O_XS + 4608)
#define SM_FLOATS (O_HS + 4608)
#define SM_BYTES  (SM_FLOATS * 4)

// ---------------- f32x2 helpers ----------------
__device__ __forceinline__ void fma2(ull& d, ull a, ull b) {
    asm("fma.rn.f32x2 %0, %1, %2, %0;" : "+l"(d) : "l"(a), "l"(b));
}
__device__ __forceinline__ float red2(ull v) {
    union { ull u; float2 f; } t; t.u = v;
    return t.f.x + t.f.y;
}
__device__ __forceinline__ ull dup2(float v) {
    ull r; asm("mov.b64 %0, {%1, %1};" : "=l"(r) : "f"(v)); return r;
}
union F4U { float4 f; ull u[2]; };

// MUFU-based transcendentals with fast division (MUFU.RCP);
// combined rel err ~1e-6 — validated far inside the 1e-3 gate (R9-R15)
__device__ __forceinline__ float sigf(float v) {
    return __fdividef(1.f, 1.f + __expf(-v));
}
__device__ __forceinline__ float tanhfast(float x) {
    x = fminf(fmaxf(x, -10.f), 10.f);
    float a = __expf(2.f * x);
    return 1.f - __fdividef(2.f, a + 1.f);
}

// ---------------- transpose_all (one launch) ----------------
#define TS0 (CDIM * NFEAT)
#define TS1 (CDIM * 768)
#define TS2 (CDIM * 768)
#define TS3 (CDIM * CDIM)
#define TS4 (CDIM * CDIM)
#define TTOT (TS0 + TS1 + TS2 + TS3 + TS4)
__global__ void transpose_all(const float* __restrict__ fd1_w, const float* __restrict__ c1_w,
                              const float* __restrict__ c2_w, const float* __restrict__ fd2_w,
                              const float* __restrict__ d1_w) {
    int idx = blockIdx.x * 256 + threadIdx.x;
    if (idx < TS0) { int n = idx / NFEAT, k = idx % NFEAT; g_fd1t[k * CDIM + n] = fd1_w[idx]; return; }
    idx -= TS0;
    if (idx < TS1) { int n = idx / 768, k = idx % 768; g_c1t[k * CDIM + n] = c1_w[idx]; return; }
    idx -= TS1;
    if (idx < TS2) { int n = idx / 768, k = idx % 768; g_c2t[k * CDIM + n] = c2_w[idx]; return; }
    idx -= TS2;
    if (idx < TS3) { int n = idx / CDIM, k = idx % CDIM; g_fd2t[k * CDIM + n] = fd2_w[idx]; return; }
    idx -= TS3;
    if (idx < TS4) { int j = idx / CDIM, k = idx % CDIM; g_d1t[k * CDIM + j] = d1_w[j * 296 + k]; }
}

// ---------------- fd1 ----------------
__global__ void fd1_kernel(const float* __restrict__ feat, const float* __restrict__ bias) {
    __shared__ float fs[NFEAT];
    int row = blockIdx.x;
    int tid = threadIdx.x;
    if (tid < NFEAT) fs[tid] = feat[row * NFEAT + tid];
    __syncthreads();
    float acc = bias[tid];
#pragma unroll
    for (int k = 0; k < NFEAT; k++)
        acc += g_fd1t[k * CDIM + tid] * fs[k];
    g_bufA[row * CDIM + tid] = tanhfast(acc);
}

// ---------------- fused conv1+conv2+fc+CP ----------------
#define CPAD 260
__global__ void __launch_bounds__(256, 1) cond_fused(
    const float* __restrict__ c1b, const float* __restrict__ c2b,
    const float* __restrict__ fcb, const float* __restrict__ d1b) {
    extern __shared__ float smf[];
    float* s_in = smf;                  // [22][260]
    float* s_m1 = smf + 22 * CPAD;      // [18][260] (reused for fc out [16][260])
    float* s_m2 = smf + 40 * CPAD;      // [16][260]

    int b = blockIdx.y;
    int t0 = blockIdx.x * 16;
    int tid = threadIdx.x;

#pragma unroll
    for (int r = 0; r < 22; r++) {
        int t = t0 + r;
        s_in[r * CPAD + tid] = (t < TFEAT) ? g_bufA[((size_t)b * TFEAT + t) * CDIM + tid] : 0.f;
    }
    __syncthreads();

    int tg = tid & 3;
    int c0 = (tid >> 2) * 4;

    // conv1 -> s_m1 rows 0..17
    {
        ull acc[5][2];
#pragma unroll
        for (int a = 0; a < 5; a++) { acc[a][0] = 0ull; acc[a][1] = 0ull; }
#pragma unroll 2
        for (int i = 0; i < CDIM; i++) {
#pragma unroll
            for (int j = 0; j < 3; j++) {
                F4U w; w.f = *reinterpret_cast<const float4*>(&g_c1t[(i * 3 + j) * CDIM + c0]);
#pragma unroll
                for (int a = 0; a < 5; a++) {
                    ull x2 = dup2(s_in[(tg + 4 * a + j) * CPAD + i]);
                    fma2(acc[a][0], w.u[0], x2);
                    fma2(acc[a][1], w.u[1], x2);
                }
            }
        }
        float4 bv = *reinterpret_cast<const float4*>(&c1b[c0]);
#pragma unroll
        for (int a = 0; a < 5; a++) {
            int r = tg + 4 * a;
            if (r < 18) {
                union { ull u; float2 f; } lo, hi;
                lo.u = acc[a][0]; hi.u = acc[a][1];
                float4 o;
                o.x = tanhfast(lo.f.x + bv.x); o.y = tanhfast(lo.f.y + bv.y);
                o.z = tanhfast(hi.f.x + bv.z); o.w = tanhfast(hi.f.y + bv.w);
                *reinterpret_cast<float4*>(&s_m1[r * CPAD + c0]) = o;
            }
        }
    }
    __syncthreads();

    // conv2 -> s_m2 rows 0..15
    {
        ull acc[4][2];
#pragma unroll
        for (int a = 0; a < 4; a++) { acc[a][0] = 0ull; acc[a][1] = 0ull; }
#pragma unroll 2
        for (int i = 0; i < CDIM; i++) {
#pragma unroll
            for (int j = 0; j < 3; j++) {
                F4U w; w.f = *reinterpret_cast<const float4*>(&g_c2t[(i * 3 + j) * CDIM + c0]);
#pragma unroll
                for (int a = 0; a < 4; a++) {
                    ull x2 = dup2(s_m1[(tg + 4 * a + j) * CPAD + i]);
                    fma2(acc[a][0], w.u[0], x2);
                    fma2(acc[a][1], w.u[1], x2);
                }
            }
        }
        float4 bv = *reinterpret_cast<const float4*>(&c2b[c0]);
#pragma unroll
        for (int a = 0; a < 4; a++) {
            int r = tg + 4 * a;
            union { ull u; float2 f; } lo, hi;
            lo.u = acc[a][0]; hi.u = acc[a][1];
            float4 o;
            o.x = tanhfast(lo.f.x + bv.x); o.y = tanhfast(lo.f.y + bv.y);
            o.z = tanhfast(hi.f.x + bv.z); o.w = tanhfast(hi.f.y + bv.w);
            *reinterpret_cast<float4*>(&s_m2[r * CPAD + c0]) = o;
        }
    }
    __syncthreads();

    // fc -> s_m1 rows 0..15 (cond stays in smem)
    {
        ull acc[4][2];
#pragma unroll
        for (int a = 0; a < 4; a++) { acc[a][0] = 0ull; acc[a][1] = 0ull; }
#pragma unroll 2
        for (int k = 0; k < CDIM; k++) {
            F4U w; w.f = *reinterpret_cast<const float4*>(&g_fd2t[k * CDIM + c0]);
#pragma unroll
            for (int a = 0; a < 4; a++) {
                ull x2 = dup2(s_m2[(tg + 4 * a) * CPAD + k]);
                fma2(acc[a][0], w.u[0], x2);
                fma2(acc[a][1], w.u[1], x2);
            }
        }
        float4 bv = *reinterpret_cast<const float4*>(&fcb[c0]);
#pragma unroll
        for (int a = 0; a < 4; a++) {
            int r = tg + 4 * a;
            union { ull u; float2 f; } lo, hi;
            lo.u = acc[a][0]; hi.u = acc[a][1];
            float4 o;
            o.x = tanhfast(lo.f.x + bv.x); o.y = tanhfast(lo.f.y + bv.y);
            o.z = tanhfast(hi.f.x + bv.z); o.w = tanhfast(hi.f.y + bv.w);
            *reinterpret_cast<float4*>(&s_m1[r * CPAD + c0]) = o;
        }
    }
    __syncthreads();

    // CP: cond @ d1t + d1_b -> g_cp (pre-activation)
    {
        ull acc[4][2];
#pragma unroll
        for (int a = 0; a < 4; a++) { acc[a][0] = 0ull; acc[a][1] = 0ull; }
#pragma unroll 2
        for (int k = 0; k < CDIM; k++) {
            F4U w; w.f = *reinterpret_cast<const float4*>(&g_d1t[k * CDIM + c0]);
#pragma unroll
            for (int a = 0; a < 4; a++) {
                ull x2 = dup2(s_m1[(tg + 4 * a) * CPAD + k]);
                fma2(acc[a][0], w.u[0], x2);
                fma2(acc[a][1], w.u[1], x2);
            }
        }
        float4 bv = *reinterpret_cast<const float4*>(&d1b[c0]);
#pragma unroll
        for (int a = 0; a < 4; a++) {
            int t = t0 + tg + 4 * a;
            if (t < 200) {
                union { ull u; float2 f; } lo, hi;
                lo.u = acc[a][0]; hi.u = acc[a][1];
                float4 o;
                o.x = lo.f.x + bv.x; o.y = lo.f.y + bv.y;
                o.z = hi.f.x + bv.z; o.w = hi.f.y + bv.w;
                *reinterpret_cast<float4*>(&g_cp[((size_t)b * 200 + t) * CDIM + c0]) = o;
            }
        }
    }
}

// ---------------- group barrier: red.release + acquire poll, padded counters ----------------
__device__ __forceinline__ void group_barrier(int grp, int target) {
    __syncthreads();
    if (threadIdx.x == 0) {
        int* addr = G_BAR(grp);
        asm volatile("red.release.gpu.global.add.s32 [%0], 1;"
                     :: "l"(addr) : "memory");
        int v;
        do {
            asm volatile("ld.acquire.gpu.global.s32 %0, [%1];"
                         : "=r"(v) : "l"(addr) : "memory");
        } while (v < target);
    }
    __syncthreads();
}

// ---------------- cooperative staging: 128 rows x 32-k chunk ----------------
struct Pre4 { float4 v[4]; };

__device__ __forceinline__ void ld4(Pre4& p, const float* __restrict__ base, int k0) {
#pragma unroll
    for (int i = 0; i < 4; i++) {
        int lin = threadIdx.x + i * NTHR;
        int row = lin >> 3, f4 = lin & 7;
        p.v[i] = __ldcg(reinterpret_cast<const float4*>(base + (size_t)row * CDIM + k0 + f4 * 4));
    }
}
__device__ __forceinline__ void st4(const Pre4& p, float* buf) {
#pragma unroll
    for (int i = 0; i < 4; i++) {
        int lin = threadIdx.x + i * NTHR;
        int row = lin >> 3, f4 = lin & 7;
        *reinterpret_cast<float4*>(buf + row * XSTR + f4 * 4) = p.v[i];
    }
}

// ---------------- persistent AR kernel: 4 groups x 32 slices, 256 thr ----------------
__global__ void __launch_bounds__(NTHR, 1) ar_kernel(
    const float* __restrict__ d1_w, const float* __restrict__ d2_w, const float* __restrict__ d2b,
    const float* __restrict__ w1i, const float* __restrict__ w1h,
    const float* __restrict__ b1i, const float* __restrict__ b1h,
    const float* __restrict__ w2i, const float* __restrict__ w2h,
    const float* __restrict__ b2i, const float* __restrict__ b2h,
    const float* __restrict__ w3i, const float* __restrict__ w3h,
    const float* __restrict__ b3i, const float* __restrict__ b3h,
    const float* __restrict__ ow,  const float* __restrict__ ob,
    const int* __restrict__ nbf,   float* __restrict__ out) {
    extern __shared__ float sm[];
    int tid = threadIdx.x;
    int s = blockIdx.x & (NSLICE - 1);
    int grp = blockIdx.x >> 5;
    int grow0 = grp * GROWS;

    // ---- resident weights ----
    for (int e = tid; e < 8 * CDIM; e += NTHR) {
        int r = e >> 8, k = e & 255;
        sm[O_WD2 + r * PDK + k] = d2_w[(s * 8 + r) * CDIM + k];
    }
    const float* wis[3] = {w1i, w2i, w3i};
    const float* whs[3] = {w1h, w2h, w3h};
    const float* bis[3] = {b1i, b2i, b3i};
    const float* bhs[3] = {b1h, b2h, b3h};
    for (int l = 0; l < 3; l++) {
        for (int e = tid; e < 24 * CDIM; e += NTHR) {
            int gr = e >> 8, k = e & 255;
            int g = gr >> 3, r = gr & 7;
            sm[O_GRU0 + l * GRU_STRIDE + gr * PDK + k] = wis[l][(g * CDIM + s * 8 + r) * CDIM + k];
            sm[O_GRU0 + l * GRU_STRIDE + 3 * 8 * PDK + gr * PDK + k] =
                whs[l][(g * CDIM + s * 8 + r) * CDIM + k];
        }
        if (tid < 24) {
            int g = tid >> 3, r = tid & 7;
            sm[O_BI0 + l * 48 + tid] = bis[l][g * CDIM + s * 8 + r];
            sm[O_BI0 + l * 48 + 24 + tid] = bhs[l][g * CDIM + s * 8 + r];
        }
    }
    if (s < 20) {
        for (int e = tid; e < 2 * CDIM; e += NTHR) {
            int r = e >> 8, k = e & 255;
            sm[O_WOW + r * PDK + k] = ow[(s * 2 + r) * CDIM + k];
        }
        if (tid < 2) sm[O_OB + tid] = ob[s * 2 + tid];
    }
    for (int e = tid; e < 8 * SUBD; e += NTHR) {
        int r = e / SUBD, q = e - r * SUBD;
        sm[O_D1P + r * 44 + q] = d1_w[(s * 8 + r) * 296 + 256 + q];
    }
    if (tid < 8) sm[O_BD2 + tid] = d2b[s * 8 + tid];
    __syncthreads();

    int c = tid & 7;
    int rq = tid >> 3;
    int scol = s * 8 + c;
    int ch_hold = scol >> 5;
    int kk_hold = scol & 31;

    float* xs = sm + O_XS;
    float* hs = sm + O_HS;

    int steps = nbf[0] * 4;
    int ostride = steps * SUBD;
    int bar_ep = 0;

    const float* CP = g_cp;
    float* t1g = g_t1 + (size_t)grow0 * CDIM;
    float* t2g = g_t2 + (size_t)grow0 * CDIM;
    float* pvg = G_PREV + (size_t)grow0 * SUBD;

    for (int st = 0; st < steps; st++) {
        int f = st >> 2;
        int p = st & 1;
        const float* h1o = G_H(p, 0) + (size_t)grow0 * CDIM;
        float*       h1n = G_H(p ^ 1, 0) + (size_t)grow0 * CDIM;
        const float* h2o = G_H(p, 1) + (size_t)grow0 * CDIM;
        float*       h2n = G_H(p ^ 1, 1) + (size_t)grow0 * CDIM;
        const float* h3o = G_H(p, 2) + (size_t)grow0 * CDIM;
        float*       h3n = G_H(p ^ 1, 2) + (size_t)grow0 * CDIM;

        // ========== d1: tanh(CP + prev @ Wp^T) ==========
        {
#pragma unroll
            for (int i = 0; i < 5; i++) {
                int lin = tid + i * NTHR;
                int row = lin / 10, f4 = lin - row * 10;
                *reinterpret_cast<float4*>(&xs[row * 44 + f4 * 4]) =
                    __ldcg(reinterpret_cast<const float4*>(&pvg[row * SUBD + f4 * 4]));
            }
            float cpv[4];
#pragma unroll
            for (int i = 0; i < 4; i++) {
                int row = grow0 + rq + 32 * i;
                cpv[i] = __ldcg(&CP[((size_t)row * 200 + f) * CDIM + scol]);
            }
            __syncthreads();
            ull A[4] = {0, 0, 0, 0};
            const float* wp = sm + O_D1P + c * 44;
#pragma unroll
            for (int k4 = 0; k4 < 10; k4++) {
                F4U W; W.f = *reinterpret_cast<const float4*>(wp + k4 * 4);
#pragma unroll
                for (int i = 0; i < 4; i++) {
                    F4U X; X.f = *reinterpret_cast<const float4*>(&xs[(rq + 32 * i) * 44 + k4 * 4]);
                    fma2(A[i], W.u[0], X.u[0]);
                    fma2(A[i], W.u[1], X.u[1]);
                }
            }
#pragma unroll
            for (int i = 0; i < 4; i++)
                __stcg(&t1g[(rq + 32 * i) * CDIM + scol], tanhfast(red2(A[i]) + cpv[i]));
        }
        group_barrier(grp, (++bar_ep) * NSLICE);

        // ========== d2 ==========
        {
            ull A[4] = {0, 0, 0, 0};
            const float* wp = sm + O_WD2 + c * PDK;
            Pre4 px;
            ld4(px, t1g, 0);
            st4(px, xs);
            __syncthreads();
            for (int ch = 0; ch < 8; ch++) {
                if (ch < 7) ld4(px, t1g, (ch + 1) * KCH);
                int k0 = ch * KCH;
#pragma unroll
                for (int k4 = 0; k4 < 8; k4++) {
                    F4U W; W.f = *reinterpret_cast<const float4*>(wp + k0 + k4 * 4);
#pragma unroll
                    for (int i = 0; i < 4; i++) {
                        F4U X; X.f = *reinterpret_cast<const float4*>(&xs[(rq + 32 * i) * XSTR + k4 * 4]);
                        fma2(A[i], W.u[0], X.u[0]);
                        fma2(A[i], W.u[1], X.u[1]);
                    }
                }
                __syncthreads();
                if (ch < 7) { st4(px, xs); __syncthreads(); }
            }
            float bb = sm[O_BD2 + c];
#pragma unroll
            for (int i = 0; i < 4; i++)
                __stcg(&t2g[(rq + 32 * i) * CDIM + scol], tanhfast(red2(A[i]) + bb));
        }
        group_barrier(grp, (++bar_ep) * NSLICE);

        // ========== 3 GRU layers ==========
        const float* xsrcs[3] = {t2g, h1n, h2n};
        const float* hsrcs[3] = {h1o, h2o, h3o};
        float*       hdsts[3] = {h1n, h2n, h3n};
        for (int gl = 0; gl < 3; gl++) {
            const float* xsrc = xsrcs[gl];
            const float* hsrc = hsrcs[gl];
            float*       hdst = hdsts[gl];

            const float* wb = sm + O_GRU0 + gl * GRU_STRIDE;
            const float* wr = wb + (0 * 8 + c) * PDK;
            const float* wz = wb + (1 * 8 + c) * PDK;
            const float* wn = wb + (2 * 8 + c) * PDK;
            const float* vr = wb + 3 * 8 * PDK + (0 * 8 + c) * PDK;
            const float* vz = wb + 3 * 8 * PDK + (1 * 8 + c) * PDK;
            const float* vn = wb + 3 * 8 * PDK + (2 * 8 + c) * PDK;

            ull Ar[4] = {0,0,0,0}, Az[4] = {0,0,0,0}, An[4] = {0,0,0,0};
            ull Br[4] = {0,0,0,0}, Bz[4] = {0,0,0,0}, Bn[4] = {0,0,0,0};
            float hold[4];

            Pre4 px, ph;
            ld4(px, xsrc, 0);
            ld4(ph, hsrc, 0);
            st4(px, xs);
            st4(ph, hs);
            __syncthreads();
            for (int ch = 0; ch < 8; ch++) {
                if (ch < 7) {
                    ld4(px, xsrc, (ch + 1) * KCH);
                    ld4(ph, hsrc, (ch + 1) * KCH);
                }
                int k0 = ch * KCH;
#pragma unroll
                for (int k4 = 0; k4 < 8; k4++) {
                    int gk = k0 + k4 * 4;
                    F4U Wr; Wr.f = *reinterpret_cast<const float4*>(wr + gk);
                    F4U Wz; Wz.f = *reinterpret_cast<const float4*>(wz + gk);
                    F4U Wn; Wn.f = *reinterpret_cast<const float4*>(wn + gk);
                    F4U Vr; Vr.f = *reinterpret_cast<const float4*>(vr + gk);
                    F4U Vz; Vz.f = *reinterpret_cast<const float4*>(vz + gk);
                    F4U Vn; Vn.f = *reinterpret_cast<const float4*>(vn + gk);
#pragma unroll
                    for (int i = 0; i < 4; i++) {
                        F4U X; X.f = *reinterpret_cast<const float4*>(&xs[(rq + 32 * i) * XSTR + k4 * 4]);
                        F4U H; H.f = *reinterpret_cast<const float4*>(&hs[(rq + 32 * i) * XSTR + k4 * 4]);
                        fma2(Ar[i], Wr.u[0], X.u[0]); fma2(Ar[i], Wr.u[1], X.u[1]);
                        fma2(Az[i], Wz.u[0], X.u[0]); fma2(Az[i], Wz.u[1], X.u[1]);
                        fma2(An[i], Wn.u[0], X.u[0]); fma2(An[i], Wn.u[1], X.u[1]);
                        fma2(Br[i], Vr.u[0], H.u[0]); fma2(Br[i], Vr.u[1], H.u[1]);
                        fma2(Bz[i], Vz.u[0], H.u[0]); fma2(Bz[i], Vz.u[1], H.u[1]);
                        fma2(Bn[i], Vn.u[0], H.u[0]); fma2(Bn[i], Vn.u[1], H.u[1]);
                    }
                }
                if (ch == ch_hold) {
#pragma unroll
                    for (int i = 0; i < 4; i++)
                        hold[i] = hs[(rq + 32 * i) * XSTR + kk_hold];
                }
                __syncthreads();
                if (ch < 7) {
                    st4(px, xs);
                    st4(ph, hs);
                    __syncthreads();
                }
            }
            const float* bi = sm + O_BI0 + gl * 48;
            const float* bh = bi + 24;
            float bir = bi[c], biz = bi[8 + c], bin = bi[16 + c];
            float bhr = bh[c], bhz = bh[8 + c], bhn = bh[16 + c];
#pragma unroll
            for (int i = 0; i < 4; i++) {
                float r = sigf(red2(Ar[i]) + bir + red2(Br[i]) + bhr);
                float z = sigf(red2(Az[i]) + biz + red2(Bz[i]) + bhz);
                float n = tanhfast(red2(An[i]) + bin + r * (red2(Bn[i]) + bhn));
                __stcg(&hdst[(rq + 32 * i) * CDIM + scol], (1.f - z) * n + z * hold[i]);
            }
            group_barrier(grp, (++bar_ep) * NSLICE);
        }

        // ========== output layer (slices 0..19: 2 cols x 128 rows) ==========
        if (s < 20) {
            int lr = tid >> 1;
            int c2 = tid & 1;
            ull A = 0ull;
            const float* wp = sm + O_WOW + c2 * PDK;
            Pre4 ph;
            ld4(ph, h3n, 0);
            st4(ph, xs);
            __syncthreads();
            for (int ch = 0; ch < 8; ch++) {
                if (ch < 7) ld4(ph, h3n, (ch + 1) * KCH);
                int k0 = ch * KCH;
#pragma unroll
                for (int k4 = 0; k4 < 8; k4++) {
                    F4U W; W.f = *reinterpret_cast<const float4*>(wp + k0 + k4 * 4);
                    F4U X; X.f = *reinterpret_cast<const float4*>(&xs[lr * XSTR + k4 * 4]);
                    fma2(A, W.u[0], X.u[0]);
                    fma2(A, W.u[1], X.u[1]);
                }
                __syncthreads();
                if (ch < 7) { st4(ph, xs); __syncthreads(); }
            }
            float v = tanhfast(red2(A) + sm[O_OB + c2]);
            int Row = grow0 + lr;
            int oc = s * 2 + c2;
            out[(size_t)Row * ostride + st * SUBD + oc] = v;
            __stcg(&pvg[lr * SUBD + oc], v);
        }
        group_barrier(grp, (++bar_ep) * NSLICE);
    }
}

// ---------------- launcher ----------------
extern "C" void kernel_launch(void* const* d_in, const int* in_sizes, int n_in,
                              void* d_out, int out_size) {
    const float* feat   = (const float*)d_in[0];
    const float* fd1_w  = (const float*)d_in[1];
    const float* fd1_b  = (const float*)d_in[2];
    const float* c1_w   = (const float*)d_in[3];
    const float* c1_b   = (const float*)d_in[4];
    const float* c2_w   = (const float*)d_in[5];
    const float* c2_b   = (const float*)d_in[6];
    const float* fd2_w  = (const float*)d_in[7];
    const float* fd2_b  = (const float*)d_in[8];
    const float* d1_w   = (const float*)d_in[9];
    const float* d1_b   = (const float*)d_in[10];
    const float* d2_w   = (const float*)d_in[11];
    const float* d2_b   = (const float*)d_in[12];
    const float* g1_wih = (const float*)d_in[13];
    const float* g1_whh = (const float*)d_in[14];
    const float* g1_bih = (const float*)d_in[15];
    const float* g1_bhh = (const float*)d_in[16];
    const float* g2_wih = (const float*)d_in[17];
    const float* g2_whh = (const float*)d_in[18];
    const float* g2_bih = (const float*)d_in[19];
    const float* g2_bhh = (const float*)d_in[20];
    const float* g3_wih = (const float*)d_in[21];
    const float* g3_whh = (const float*)d_in[22];
    const float* g3_bih = (const float*)d_in[23];
    const float* g3_bhh = (const float*)d_in[24];
    const float* ow     = (const float*)d_in[25];
    const float* ob     = (const float*)d_in[26];
    const int*   nbf    = (const int*)d_in[27];
    float* out = (float*)d_out;

    float* pState;
    cudaGetSymbolAddress((void**)&pState, g_state);

    static bool attr_set = false;
    if (!attr_set) {
        cudaFuncSetAttribute(cond_fused, cudaFuncAttributeMaxDynamicSharedMemorySize,
                             56 * CPAD * 4);
        cudaFuncSetAttribute(ar_kernel, cudaFuncAttributeMaxDynamicSharedMemorySize, SM_BYTES);
        attr_set = true;
    }

    cudaMemsetAsync(pState, 0, STATE_TOT * sizeof(float));
    transpose_all<<<(TTOT + 255) / 256, 256>>>(fd1_w, c1_w, c2_w, fd2_w, d1_w);
    fd1_kernel<<<BATCH * TFEAT, 256>>>(feat, fd1_b);
    cond_fused<<<dim3(13, BATCH), 256, 56 * CPAD * 4>>>(c1_b, c2_b, fd2_b, d1_b);
    ar_kernel<<<NCTA, NTHR, SM_BYTES>>>(
        d1_w, d2_w, d2_b,
        g1_wih, g1_whh, g1_bih, g1_bhh,
        g2_wih, g2_whh, g2_bih, g2_bhh,
        g3_wih, g3_whh, g3_bih, g3_bhh,
        ow, ob, nbf, out);
}

// round 17
// speedup vs baseline: 1.0956x; 1.0287x over previous
#include <cuda_runtime.h>
#include <math.h>

typedef unsigned long long ull;

#define BATCH 512
#define TFEAT 204
#define NFEAT 20
#define CDIM  256
#define SUBD  40
#define NSLICE 32
#define NGRP   4
#define GROWS  128
#define NCTA   128
#define NTHR   256
#define KCH    32
#define XSTR   36

// ---------------- device globals ----------------
__device__ float g_bufA[BATCH * TFEAT * CDIM];   // fd1 out
__device__ float g_cp[BATCH * 200 * CDIM];       // CP = cond @ d1_w[:, :256]^T + d1_b

__device__ float g_fd1t[NFEAT * CDIM];
__device__ float g_c1t[768 * CDIM];
__device__ float g_c2t[768 * CDIM];
__device__ float g_fd2t[CDIM * CDIM];
__device__ float g_d1t[CDIM * CDIM];             // transposed first-256-k of d1_w

__device__ float g_t1[BATCH * CDIM];
__device__ float g_t2[BATCH * CDIM];

// zeroed state: h ping-pong(6 planes) + prev + padded barrier counters (one memset)
#define STATE_H     0
#define STATE_PREV  (6 * BATCH * CDIM)
#define STATE_BAR   (STATE_PREV + BATCH * SUBD)
#define STATE_TOT   (STATE_BAR + NGRP * 32)
__device__ float g_state[STATE_TOT];
#define G_H(p, l)   (g_state + ((p) * 3 + (l)) * (BATCH * CDIM))
#define G_PREV      (g_state + STATE_PREV)
#define G_BAR(grp)  ((int*)(g_state + STATE_BAR) + (grp) * 32)   // 128B apart

// ---------------- smem layout for AR (floats) ----------------
#define PDK 260
#define O_WD2  0
#define O_GRU0 2080
#define GRU_STRIDE 12480
#define O_WOW  (O_GRU0 + 3 * GRU_STRIDE)  // 39520
#define O_D1P  (O_WOW + 520)              // [8][44]
#define O_BD2  (O_D1P + 352)
#define O_BI0  (O_BD2 + 8)
#define O_OB   (O_BI0 + 144)
#define O_XS   40548
#define O_HS   (O_XS + 4608)
#define SM_FLOATS (O_HS + 4608)
#define SM_BYTES  (SM_FLOATS * 4)

// ---------------- f32x2 helpers ----------------
__device__ __forceinline__ void fma2(ull& d, ull a, ull b) {
    asm("fma.rn.f32x2 %0, %1, %2, %0;" : "+l"(d) : "l"(a), "l"(b));
}
__device__ __forceinline__ float red2(ull v) {
    union { ull u; float2 f; } t; t.u = v;
    return t.f.x + t.f.y;
}
__device__ __forceinline__ ull dup2(float v) {
    ull r; asm("mov.b64 %0, {%1, %1};" : "=l"(r) : "f"(v)); return r;
}
union F4U { float4 f; ull u[2]; };

// MUFU-based transcendentals, fast division (MUFU.RCP), no clamp needed:
// x->+inf: a=inf -> 1;  x->-inf: a=0 -> -1.  Combined rel err ~1e-6 (gate 1e-3).
__device__ __forceinline__ float sigf(float v) {
    return __fdividef(1.f, 1.f + __expf(-v));
}
__device__ __forceinline__ float tanhfast(float x) {
    float a = __expf(2.f * x);
    return 1.f - __fdividef(2.f, a + 1.f);
}

// ---------------- transpose_all (one launch) ----------------
#define TS0 (CDIM * NFEAT)
#define TS1 (CDIM * 768)
#define TS2 (CDIM * 768)
#define TS3 (CDIM * CDIM)
#define TS4 (CDIM * CDIM)
#define TTOT (TS0 + TS1 + TS2 + TS3 + TS4)
__global__ void transpose_all(const float* __restrict__ fd1_w, const float* __restrict__ c1_w,
                              const float* __restrict__ c2_w, const float* __restrict__ fd2_w,
                              const float* __restrict__ d1_w) {
    int idx = blockIdx.x * 256 + threadIdx.x;
    if (idx < TS0) { int n = idx / NFEAT, k = idx % NFEAT; g_fd1t[k * CDIM + n] = fd1_w[idx]; return; }
    idx -= TS0;
    if (idx < TS1) { int n = idx / 768, k = idx % 768; g_c1t[k * CDIM + n] = c1_w[idx]; return; }
    idx -= TS1;
    if (idx < TS2) { int n = idx / 768, k = idx % 768; g_c2t[k * CDIM + n] = c2_w[idx]; return; }
    idx -= TS2;
    if (idx < TS3) { int n = idx / CDIM, k = idx % CDIM; g_fd2t[k * CDIM + n] = fd2_w[idx]; return; }
    idx -= TS3;
    if (idx < TS4) { int j = idx / CDIM, k = idx % CDIM; g_d1t[k * CDIM + j] = d1_w[j * 296 + k]; }
}

// ---------------- fd1 ----------------
__global__ void fd1_kernel(const float* __restrict__ feat, const float* __restrict__ bias) {
    __shared__ float fs[NFEAT];
    int row = blockIdx.x;
    int tid = threadIdx.x;
    if (tid < NFEAT) fs[tid] = feat[row * NFEAT + tid];
    __syncthreads();
    float acc = bias[tid];
#pragma unroll
    for (int k = 0; k < NFEAT; k++)
        acc += g_fd1t[k * CDIM + tid] * fs[k];
    g_bufA[row * CDIM + tid] = tanhfast(acc);
}

// ---------------- fused conv1+conv2+fc+CP ----------------
#define CPAD 260
__global__ void __launch_bounds__(256, 1) cond_fused(
    const float* __restrict__ c1b, const float* __restrict__ c2b,
    const float* __restrict__ fcb, const float* __restrict__ d1b) {
    extern __shared__ float smf[];
    float* s_in = smf;                  // [22][260]
    float* s_m1 = smf + 22 * CPAD;      // [18][260] (reused for fc out [16][260])
    float* s_m2 = smf + 40 * CPAD;      // [16][260]

    int b = blockIdx.y;
    int t0 = blockIdx.x * 16;
    int tid = threadIdx.x;

#pragma unroll
    for (int r = 0; r < 22; r++) {
        int t = t0 + r;
        s_in[r * CPAD + tid] = (t < TFEAT) ? g_bufA[((size_t)b * TFEAT + t) * CDIM + tid] : 0.f;
    }
    __syncthreads();

    int tg = tid & 3;
    int c0 = (tid >> 2) * 4;

    // conv1 -> s_m1 rows 0..17
    {
        ull acc[5][2];
#pragma unroll
        for (int a = 0; a < 5; a++) { acc[a][0] = 0ull; acc[a][1] = 0ull; }
#pragma unroll 2
        for (int i = 0; i < CDIM; i++) {
#pragma unroll
            for (int j = 0; j < 3; j++) {
                F4U w; w.f = *reinterpret_cast<const float4*>(&g_c1t[(i * 3 + j) * CDIM + c0]);
#pragma unroll
                for (int a = 0; a < 5; a++) {
                    ull x2 = dup2(s_in[(tg + 4 * a + j) * CPAD + i]);
                    fma2(acc[a][0], w.u[0], x2);
                    fma2(acc[a][1], w.u[1], x2);
                }
            }
        }
        float4 bv = *reinterpret_cast<const float4*>(&c1b[c0]);
#pragma unroll
        for (int a = 0; a < 5; a++) {
            int r = tg + 4 * a;
            if (r < 18) {
                union { ull u; float2 f; } lo, hi;
                lo.u = acc[a][0]; hi.u = acc[a][1];
                float4 o;
                o.x = tanhfast(lo.f.x + bv.x); o.y = tanhfast(lo.f.y + bv.y);
                o.z = tanhfast(hi.f.x + bv.z); o.w = tanhfast(hi.f.y + bv.w);
                *reinterpret_cast<float4*>(&s_m1[r * CPAD + c0]) = o;
            }
        }
    }
    __syncthreads();

    // conv2 -> s_m2 rows 0..15
    {
        ull acc[4][2];
#pragma unroll
        for (int a = 0; a < 4; a++) { acc[a][0] = 0ull; acc[a][1] = 0ull; }
#pragma unroll 2
        for (int i = 0; i < CDIM; i++) {
#pragma unroll
            for (int j = 0; j < 3; j++) {
                F4U w; w.f = *reinterpret_cast<const float4*>(&g_c2t[(i * 3 + j) * CDIM + c0]);
#pragma unroll
                for (int a = 0; a < 4; a++) {
                    ull x2 = dup2(s_m1[(tg + 4 * a + j) * CPAD + i]);
                    fma2(acc[a][0], w.u[0], x2);
                    fma2(acc[a][1], w.u[1], x2);
                }
            }
        }
        float4 bv = *reinterpret_cast<const float4*>(&c2b[c0]);
#pragma unroll
        for (int a = 0; a < 4; a++) {
            int r = tg + 4 * a;
            union { ull u; float2 f; } lo, hi;
            lo.u = acc[a][0]; hi.u = acc[a][1];
            float4 o;
            o.x = tanhfast(lo.f.x + bv.x); o.y = tanhfast(lo.f.y + bv.y);
            o.z = tanhfast(hi.f.x + bv.z); o.w = tanhfast(hi.f.y + bv.w);
            *reinterpret_cast<float4*>(&s_m2[r * CPAD + c0]) = o;
        }
    }
    __syncthreads();

    // fc -> s_m1 rows 0..15 (cond stays in smem)
    {
        ull acc[4][2];
#pragma unroll
        for (int a = 0; a < 4; a++) { acc[a][0] = 0ull; acc[a][1] = 0ull; }
#pragma unroll 2
        for (int k = 0; k < CDIM; k++) {
            F4U w; w.f = *reinterpret_cast<const float4*>(&g_fd2t[k * CDIM + c0]);
#pragma unroll
            for (int a = 0; a < 4; a++) {
                ull x2 = dup2(s_m2[(tg + 4 * a) * CPAD + k]);
                fma2(acc[a][0], w.u[0], x2);
                fma2(acc[a][1], w.u[1], x2);
            }
        }
        float4 bv = *reinterpret_cast<const float4*>(&fcb[c0]);
#pragma unroll
        for (int a = 0; a < 4; a++) {
            int r = tg + 4 * a;
            union { ull u; float2 f; } lo, hi;
            lo.u = acc[a][0]; hi.u = acc[a][1];
            float4 o;
            o.x = tanhfast(lo.f.x + bv.x); o.y = tanhfast(lo.f.y + bv.y);
            o.z = tanhfast(hi.f.x + bv.z); o.w = tanhfast(hi.f.y + bv.w);
            *reinterpret_cast<float4*>(&s_m1[r * CPAD + c0]) = o;
        }
    }
    __syncthreads();

    // CP: cond @ d1t + d1_b -> g_cp (pre-activation)
    {
        ull acc[4][2];
#pragma unroll
        for (int a = 0; a < 4; a++) { acc[a][0] = 0ull; acc[a][1] = 0ull; }
#pragma unroll 2
        for (int k = 0; k < CDIM; k++) {
            F4U w; w.f = *reinterpret_cast<const float4*>(&g_d1t[k * CDIM + c0]);
#pragma unroll
            for (int a = 0; a < 4; a++) {
                ull x2 = dup2(s_m1[(tg + 4 * a) * CPAD + k]);
                fma2(acc[a][0], w.u[0], x2);
                fma2(acc[a][1], w.u[1], x2);
            }
        }
        float4 bv = *reinterpret_cast<const float4*>(&d1b[c0]);
#pragma unroll
        for (int a = 0; a < 4; a++) {
            int t = t0 + tg + 4 * a;
            if (t < 200) {
                union { ull u; float2 f; } lo, hi;
                lo.u = acc[a][0]; hi.u = acc[a][1];
                float4 o;
                o.x = lo.f.x + bv.x; o.y = lo.f.y + bv.y;
                o.z = hi.f.x + bv.z; o.w = hi.f.y + bv.w;
                *reinterpret_cast<float4*>(&g_cp[((size_t)b * 200 + t) * CDIM + c0]) = o;
            }
        }
    }
}

// ---------------- group barrier: red.release + acquire poll, padded counters ----------------
__device__ __forceinline__ void group_barrier(int grp, int target) {
    __syncthreads();
    if (threadIdx.x == 0) {
        int* addr = G_BAR(grp);
        asm volatile("red.release.gpu.global.add.s32 [%0], 1;"
                     :: "l"(addr) : "memory");
        int v;
        do {
            asm volatile("ld.acquire.gpu.global.s32 %0, [%1];"
                         : "=r"(v) : "l"(addr) : "memory");
        } while (v < target);
    }
    __syncthreads();
}

// ---------------- cooperative staging: 128 rows x 32-k chunk ----------------
struct Pre4 { float4 v[4]; };

__device__ __forceinline__ void ld4(Pre4& p, const float* __restrict__ base, int k0) {
#pragma unroll
    for (int i = 0; i < 4; i++) {
        int lin = threadIdx.x + i * NTHR;
        int row = lin >> 3, f4 = lin & 7;
        p.v[i] = __ldcg(reinterpret_cast<const float4*>(base + (size_t)row * CDIM + k0 + f4 * 4));
    }
}
__device__ __forceinline__ void st4(const Pre4& p, float* buf) {
#pragma unroll
    for (int i = 0; i < 4; i++) {
        int lin = threadIdx.x + i * NTHR;
        int row = lin >> 3, f4 = lin & 7;
        *reinterpret_cast<float4*>(buf + row * XSTR + f4 * 4) = p.v[i];
    }
}

// ---------------- persistent AR kernel: 4 groups x 32 slices, 256 thr ----------------
__global__ void __launch_bounds__(NTHR, 1) ar_kernel(
    const float* __restrict__ d1_w, const float* __restrict__ d2_w, const float* __restrict__ d2b,
    const float* __restrict__ w1i, const float* __restrict__ w1h,
    const float* __restrict__ b1i, const float* __restrict__ b1h,
    const float* __restrict__ w2i, const float* __restrict__ w2h,
    const float* __restrict__ b2i, const float* __restrict__ b2h,
    const float* __restrict__ w3i, const float* __restrict__ w3h,
    const float* __restrict__ b3i, const float* __restrict__ b3h,
    const float* __restrict__ ow,  const float* __restrict__ ob,
    const int* __restrict__ nbf,   float* __restrict__ out) {
    extern __shared__ float sm[];
    int tid = threadIdx.x;
    int s = blockIdx.x & (NSLICE - 1);
    int grp = blockIdx.x >> 5;
    int grow0 = grp * GROWS;

    // ---- resident weights ----
    for (int e = tid; e < 8 * CDIM; e += NTHR) {
        int r = e >> 8, k = e & 255;
        sm[O_WD2 + r * PDK + k] = d2_w[(s * 8 + r) * CDIM + k];
    }
    const float* wis[3] = {w1i, w2i, w3i};
    const float* whs[3] = {w1h, w2h, w3h};
    const float* bis[3] = {b1i, b2i, b3i};
    const float* bhs[3] = {b1h, b2h, b3h};
    for (int l = 0; l < 3; l++) {
        for (int e = tid; e < 24 * CDIM; e += NTHR) {
            int gr = e >> 8, k = e & 255;
            int g = gr >> 3, r = gr & 7;
            sm[O_GRU0 + l * GRU_STRIDE + gr * PDK + k] = wis[l][(g * CDIM + s * 8 + r) * CDIM + k];
            sm[O_GRU0 + l * GRU_STRIDE + 3 * 8 * PDK + gr * PDK + k] =
                whs[l][(g * CDIM + s * 8 + r) * CDIM + k];
        }
        if (tid < 24) {
            int g = tid >> 3, r = tid & 7;
            sm[O_BI0 + l * 48 + tid] = bis[l][g * CDIM + s * 8 + r];
            sm[O_BI0 + l * 48 + 24 + tid] = bhs[l][g * CDIM + s * 8 + r];
        }
    }
    if (s < 20) {
        for (int e = tid; e < 2 * CDIM; e += NTHR) {
            int r = e >> 8, k = e & 255;
            sm[O_WOW + r * PDK + k] = ow[(s * 2 + r) * CDIM + k];
        }
        if (tid < 2) sm[O_OB + tid] = ob[s * 2 + tid];
    }
    for (int e = tid; e < 8 * SUBD; e += NTHR) {
        int r = e / SUBD, q = e - r * SUBD;
        sm[O_D1P + r * 44 + q] = d1_w[(s * 8 + r) * 296 + 256 + q];
    }
    if (tid < 8) sm[O_BD2 + tid] = d2b[s * 8 + tid];
    __syncthreads();

    int c = tid & 7;
    int rq = tid >> 3;
    int scol = s * 8 + c;
    int ch_hold = scol >> 5;
    int kk_hold = scol & 31;

    float* xs = sm + O_XS;
    float* hs = sm + O_HS;

    int steps = nbf[0] * 4;
    int ostride = steps * SUBD;
    int bar_ep = 0;

    const float* CP = g_cp;
    float* t1g = g_t1 + (size_t)grow0 * CDIM;
    float* t2g = g_t2 + (size_t)grow0 * CDIM;
    float* pvg = G_PREV + (size_t)grow0 * SUBD;

    for (int st = 0; st < steps; st++) {
        int f = st >> 2;
        int p = st & 1;
        const float* h1o = G_H(p, 0) + (size_t)grow0 * CDIM;
        float*       h1n = G_H(p ^ 1, 0) + (size_t)grow0 * CDIM;
        const float* h2o = G_H(p, 1) + (size_t)grow0 * CDIM;
        float*       h2n = G_H(p ^ 1, 1) + (size_t)grow0 * CDIM;
        const float* h3o = G_H(p, 2) + (size_t)grow0 * CDIM;
        float*       h3n = G_H(p ^ 1, 2) + (size_t)grow0 * CDIM;

        // ========== d1: tanh(CP + prev @ Wp^T) ==========
        {
#pragma unroll
            for (int i = 0; i < 5; i++) {
                int lin = tid + i * NTHR;
                int row = lin / 10, f4 = lin - row * 10;
                *reinterpret_cast<float4*>(&xs[row * 44 + f4 * 4]) =
                    __ldcg(reinterpret_cast<const float4*>(&pvg[row * SUBD + f4 * 4]));
            }
            float cpv[4];
#pragma unroll
            for (int i = 0; i < 4; i++) {
                int row = grow0 + rq + 32 * i;
                cpv[i] = __ldcg(&CP[((size_t)row * 200 + f) * CDIM + scol]);
            }
            __syncthreads();
            ull A[4] = {0, 0, 0, 0};
            const float* wp = sm + O_D1P + c * 44;
#pragma unroll
            for (int k4 = 0; k4 < 10; k4++) {
                F4U W; W.f = *reinterpret_cast<const float4*>(wp + k4 * 4);
#pragma unroll
                for (int i = 0; i < 4; i++) {
                    F4U X; X.f = *reinterpret_cast<const float4*>(&xs[(rq + 32 * i) * 44 + k4 * 4]);
                    fma2(A[i], W.u[0], X.u[0]);
                    fma2(A[i], W.u[1], X.u[1]);
                }
            }
#pragma unroll
            for (int i = 0; i < 4; i++)
                __stcg(&t1g[(rq + 32 * i) * CDIM + scol], tanhfast(red2(A[i]) + cpv[i]));
        }
        group_barrier(grp, (++bar_ep) * NSLICE);

        // ========== d2 ==========
        {
            ull A[4] = {0, 0, 0, 0};
            const float* wp = sm + O_WD2 + c * PDK;
            Pre4 px;
            ld4(px, t1g, 0);
            st4(px, xs);
            __syncthreads();
            for (int ch = 0; ch < 8; ch++) {
                if (ch < 7) ld4(px, t1g, (ch + 1) * KCH);
                int k0 = ch * KCH;
#pragma unroll
                for (int k4 = 0; k4 < 8; k4++) {
                    F4U W; W.f = *reinterpret_cast<const float4*>(wp + k0 + k4 * 4);
#pragma unroll
                    for (int i = 0; i < 4; i++) {
                        F4U X; X.f = *reinterpret_cast<const float4*>(&xs[(rq + 32 * i) * XSTR + k4 * 4]);
                        fma2(A[i], W.u[0], X.u[0]);
                        fma2(A[i], W.u[1], X.u[1]);
                    }
                }
                __syncthreads();
                if (ch < 7) { st4(px, xs); __syncthreads(); }
            }
            float bb = sm[O_BD2 + c];
#pragma unroll
            for (int i = 0; i < 4; i++)
                __stcg(&t2g[(rq + 32 * i) * CDIM + scol], tanhfast(red2(A[i]) + bb));
        }
        group_barrier(grp, (++bar_ep) * NSLICE);

        // ========== 3 GRU layers ==========
        const float* xsrcs[3] = {t2g, h1n, h2n};
        const float* hsrcs[3] = {h1o, h2o, h3o};
        float*       hdsts[3] = {h1n, h2n, h3n};
        for (int gl = 0; gl < 3; gl++) {
            const float* xsrc = xsrcs[gl];
            const float* hsrc = hsrcs[gl];
            float*       hdst = hdsts[gl];

            const float* wb = sm + O_GRU0 + gl * GRU_STRIDE;
            const float* wr = wb + (0 * 8 + c) * PDK;
            const float* wz = wb + (1 * 8 + c) * PDK;
            const float* wn = wb + (2 * 8 + c) * PDK;
            const float* vr = wb + 3 * 8 * PDK + (0 * 8 + c) * PDK;
            const float* vz = wb + 3 * 8 * PDK + (1 * 8 + c) * PDK;
            const float* vn = wb + 3 * 8 * PDK + (2 * 8 + c) * PDK;

            ull Ar[4] = {0,0,0,0}, Az[4] = {0,0,0,0}, An[4] = {0,0,0,0};
            ull Br[4] = {0,0,0,0}, Bz[4] = {0,0,0,0}, Bn[4] = {0,0,0,0};
            float hold[4];

            Pre4 px, ph;
            ld4(px, xsrc, 0);
            ld4(ph, hsrc, 0);
            st4(px, xs);
            st4(ph, hs);
            __syncthreads();
            for (int ch = 0; ch < 8; ch++) {
                if (ch < 7) {
                    ld4(px, xsrc, (ch + 1) * KCH);
                    ld4(ph, hsrc, (ch + 1) * KCH);
                }
                int k0 = ch * KCH;
#pragma unroll
                for (int k4 = 0; k4 < 8; k4++) {
                    int gk = k0 + k4 * 4;
                    F4U Wr; Wr.f = *reinterpret_cast<const float4*>(wr + gk);
                    F4U Wz; Wz.f = *reinterpret_cast<const float4*>(wz + gk);
                    F4U Wn; Wn.f = *reinterpret_cast<const float4*>(wn + gk);
                    F4U Vr; Vr.f = *reinterpret_cast<const float4*>(vr + gk);
                    F4U Vz; Vz.f = *reinterpret_cast<const float4*>(vz + gk);
                    F4U Vn; Vn.f = *reinterpret_cast<const float4*>(vn + gk);
#pragma unroll
                    for (int i = 0; i < 4; i++) {
                        F4U X; X.f = *reinterpret_cast<const float4*>(&xs[(rq + 32 * i) * XSTR + k4 * 4]);
                        F4U H; H.f = *reinterpret_cast<const float4*>(&hs[(rq + 32 * i) * XSTR + k4 * 4]);
                        fma2(Ar[i], Wr.u[0], X.u[0]); fma2(Ar[i], Wr.u[1], X.u[1]);
                        fma2(Az[i], Wz.u[0], X.u[0]); fma2(Az[i], Wz.u[1], X.u[1]);
                        fma2(An[i], Wn.u[0], X.u[0]); fma2(An[i], Wn.u[1], X.u[1]);
                        fma2(Br[i], Vr.u[0], H.u[0]); fma2(Br[i], Vr.u[1], H.u[1]);
                        fma2(Bz[i], Vz.u[0], H.u[0]); fma2(Bz[i], Vz.u[1], H.u[1]);
                        fma2(Bn[i], Vn.u[0], H.u[0]); fma2(Bn[i], Vn.u[1], H.u[1]);
                    }
                }
                if (ch == ch_hold) {
#pragma unroll
                    for (int i = 0; i < 4; i++)
                        hold[i] = hs[(rq + 32 * i) * XSTR + kk_hold];
                }
                __syncthreads();
                if (ch < 7) {
                    st4(px, xs);
                    st4(ph, hs);
                    __syncthreads();
                }
            }
            const float* bi = sm + O_BI0 + gl * 48;
            const float* bh = bi + 24;
            float bir = bi[c], biz = bi[8 + c], bin = bi[16 + c];
            float bhr = bh[c], bhz = bh[8 + c], bhn = bh[16 + c];
#pragma unroll
            for (int i = 0; i < 4; i++) {
                float r = sigf(red2(Ar[i]) + bir + red2(Br[i]) + bhr);
                float z = sigf(red2(Az[i]) + biz + red2(Bz[i]) + bhz);
                float n = tanhfast(red2(An[i]) + bin + r * (red2(Bn[i]) + bhn));
                __stcg(&hdst[(rq + 32 * i) * CDIM + scol], (1.f - z) * n + z * hold[i]);
            }
            group_barrier(grp, (++bar_ep) * NSLICE);
        }

        // ========== output layer (slices 0..19: 2 cols x 128 rows) ==========
        if (s < 20) {
            int lr = tid >> 1;
            int c2 = tid & 1;
            ull A = 0ull;
            const float* wp = sm + O_WOW + c2 * PDK;
            Pre4 ph;
            ld4(ph, h3n, 0);
            st4(ph, xs);
            __syncthreads();
            for (int ch = 0; ch < 8; ch++) {
                if (ch < 7) ld4(ph, h3n, (ch + 1) * KCH);
                int k0 = ch * KCH;
#pragma unroll
                for (int k4 = 0; k4 < 8; k4++) {
                    F4U W; W.f = *reinterpret_cast<const float4*>(wp + k0 + k4 * 4);
                    F4U X; X.f = *reinterpret_cast<const float4*>(&xs[lr * XSTR + k4 * 4]);
                    fma2(A, W.u[0], X.u[0]);
                    fma2(A, W.u[1], X.u[1]);
                }
                __syncthreads();
                if (ch < 7) { st4(ph, xs); __syncthreads(); }
            }
            float v = tanhfast(red2(A) + sm[O_OB + c2]);
            int Row = grow0 + lr;
            int oc = s * 2 + c2;
            out[(size_t)Row * ostride + st * SUBD + oc] = v;
            __stcg(&pvg[lr * SUBD + oc], v);
        }
        group_barrier(grp, (++bar_ep) * NSLICE);
    }
}

// ---------------- launcher ----------------
extern "C" void kernel_launch(void* const* d_in, const int* in_sizes, int n_in,
                              void* d_out, int out_size) {
    const float* feat   = (const float*)d_in[0];
    const float* fd1_w  = (const float*)d_in[1];
    const float* fd1_b  = (const float*)d_in[2];
    const float* c1_w   = (const float*)d_in[3];
    const float* c1_b   = (const float*)d_in[4];
    const float* c2_w   = (const float*)d_in[5];
    const float* c2_b   = (const float*)d_in[6];
    const float* fd2_w  = (const float*)d_in[7];
    const float* fd2_b  = (const float*)d_in[8];
    const float* d1_w   = (const float*)d_in[9];
    const float* d1_b   = (const float*)d_in[10];
    const float* d2_w   = (const float*)d_in[11];
    const float* d2_b   = (const float*)d_in[12];
    const float* g1_wih = (const float*)d_in[13];
    const float* g1_whh = (const float*)d_in[14];
    const float* g1_bih = (const float*)d_in[15];
    const float* g1_bhh = (const float*)d_in[16];
    const float* g2_wih = (const float*)d_in[17];
    const float* g2_whh = (const float*)d_in[18];
    const float* g2_bih = (const float*)d_in[19];
    const float* g2_bhh = (const float*)d_in[20];
    const float* g3_wih = (const float*)d_in[21];
    const float* g3_whh = (const float*)d_in[22];
    const float* g3_bih = (const float*)d_in[23];
    const float* g3_bhh = (const float*)d_in[24];
    const float* ow     = (const float*)d_in[25];
    const float* ob     = (const float*)d_in[26];
    const int*   nbf    = (const int*)d_in[27];
    float* out = (float*)d_out;

    float* pState;
    cudaGetSymbolAddress((void**)&pState, g_state);

    static bool attr_set = false;
    if (!attr_set) {
        cudaFuncSetAttribute(cond_fused, cudaFuncAttributeMaxDynamicSharedMemorySize,
                             56 * CPAD * 4);
        cudaFuncSetAttribute(ar_kernel, cudaFuncAttributeMaxDynamicSharedMemorySize, SM_BYTES);
        attr_set = true;
    }

    cudaMemsetAsync(pState, 0, STATE_TOT * sizeof(float));
    transpose_all<<<(TTOT + 255) / 256, 256>>>(fd1_w, c1_w, c2_w, fd2_w, d1_w);
    fd1_kernel<<<BATCH * TFEAT, 256>>>(feat, fd1_b);
    cond_fused<<<dim3(13, BATCH), 256, 56 * CPAD * 4>>>(c1_b, c2_b, fd2_b, d1_b);
    ar_kernel<<<NCTA, NTHR, SM_BYTES>>>(
        d1_w, d2_w, d2_b,
        g1_wih, g1_whh, g1_bih, g1_bhh,
        g2_wih, g2_whh, g2_bih, g2_bhh,
        g3_wih, g3_whh, g3_bih, g3_bhh,
        ow, ob, nbf, out);
}